// round 3
// baseline (speedup 1.0000x reference)
#include <cuda_runtime.h>
#include <cstdint>
#include <cstddef>

#define N_NODES 50000
#define N_EDGES 800000
#define N_LINE  800000
#define D 128
#define NL 3

// ---------------- scratch (static device globals; no allocations) ----------------
__device__ float g_nf0[(size_t)N_NODES * D];
__device__ float g_nf1[(size_t)N_NODES * D];
__device__ float g_ef0[(size_t)N_EDGES * D];
__device__ float g_ef1[(size_t)N_EDGES * D];
__device__ float g_an [(size_t)N_NODES * D];
__device__ float g_a1n[(size_t)N_NODES * D];
__device__ float g_ae [(size_t)N_EDGES * D];
__device__ float g_a1e[(size_t)N_EDGES * D];
__device__ unsigned int g_pool[2 * D];

// ---------------- gather + scatter-add (one warp per edge-row, float4 RED) -------
__global__ void scatter_add_k(const float* __restrict__ src, float* __restrict__ dst,
                              const int* __restrict__ gidx, const int* __restrict__ sidx,
                              int count)
{
    int lane  = threadIdx.x & 31;
    int warp  = (blockIdx.x * blockDim.x + threadIdx.x) >> 5;
    int nwarp = (gridDim.x * blockDim.x) >> 5;
    for (int e = warp; e < count; e += nwarp) {
        int g = gidx[e];
        int s = sidx[e];
        float4 v = *((const float4*)(src + (size_t)g * D) + lane);
        atomicAdd((float4*)(dst + (size_t)s * D) + lane, v);
    }
}

// ---------------- fused SAGE update: out = norm(x@Wc + a1@Wn + a2@We + b), leaky --
// BM=64, BN=128 (full row in block), BK=32, 256 threads, 8x4 accum per thread.
__global__ __launch_bounds__(256) void sage_gemm_k(
    const float* __restrict__ x,  const float* __restrict__ a1, const float* __restrict__ a2,
    const float* __restrict__ Wc, const float* __restrict__ Wn, const float* __restrict__ We,
    const float* __restrict__ bc, const float* __restrict__ bn, const float* __restrict__ be,
    float* __restrict__ out, int M, int act)
{
    __shared__ float buf[8192];   // loop: Xs=buf[0:2048), Ws=buf[2048:6144); epilogue: Os=buf[0:8192)
    __shared__ float bsum[D];
    float* Xs = buf;
    float* Ws = buf + 2048;

    int t  = threadIdx.x;
    int tx = t & 31, ty = t >> 5;
    int row0 = blockIdx.x * 64;

    if (t < D) bsum[t] = bc[t] + bn[t] + be[t];

    float acc[8][4];
#pragma unroll
    for (int i = 0; i < 8; i++)
#pragma unroll
        for (int j = 0; j < 4; j++) acc[i][j] = 0.f;

    const float* srcs[3] = { x, a1, a2 };
    const float* ws[3]   = { Wc, Wn, We };

    for (int c = 0; c < 12; c++) {
        const float* src = srcs[c >> 2];
        const float* w   = ws[c >> 2];
        int kofs = (c & 3) * 32;

        __syncthreads();
        {   // X tile: 64 x 32 floats (512 float4), 2 per thread
            int r  = t >> 3;
            int c4 = (t & 7) * 4;
#pragma unroll
            for (int h = 0; h < 2; h++) {
                int row = r + h * 32;
                float4 v = make_float4(0.f, 0.f, 0.f, 0.f);
                if (row0 + row < M)
                    v = *(const float4*)(src + (size_t)(row0 + row) * D + kofs + c4);
                *(float4*)(Xs + row * 32 + c4) = v;
            }
            // W tile: 32 x 128 floats (1024 float4), 4 per thread
#pragma unroll
            for (int h = 0; h < 4; h++) {
                int idx = t + h * 256;
                int wr = idx >> 5, wc = (idx & 31) * 4;
                *(float4*)(Ws + wr * 128 + wc) =
                    *(const float4*)(w + (size_t)(kofs + wr) * D + wc);
            }
        }
        __syncthreads();

#pragma unroll
        for (int kk = 0; kk < 32; kk++) {
            float a[8];
#pragma unroll
            for (int i = 0; i < 8; i++) a[i] = Xs[(ty * 8 + i) * 32 + kk];
            float4 bv = *(float4*)(Ws + kk * 128 + tx * 4);
#pragma unroll
            for (int i = 0; i < 8; i++) {
                acc[i][0] += a[i] * bv.x;
                acc[i][1] += a[i] * bv.y;
                acc[i][2] += a[i] * bv.z;
                acc[i][3] += a[i] * bv.w;
            }
        }
    }
    __syncthreads();

    // stage biased output tile into smem
#pragma unroll
    for (int i = 0; i < 8; i++) {
        float4 o;
        o.x = acc[i][0] + bsum[tx * 4 + 0];
        o.y = acc[i][1] + bsum[tx * 4 + 1];
        o.z = acc[i][2] + bsum[tx * 4 + 2];
        o.w = acc[i][3] + bsum[tx * 4 + 3];
        *(float4*)(buf + (ty * 8 + i) * 128 + tx * 4) = o;
    }
    __syncthreads();

    // warp ty normalizes rows ty*8 .. ty*8+7 (full 128-wide row per warp)
    for (int r = 0; r < 8; r++) {
        int row = ty * 8 + r;
        if (row0 + row >= M) break;
        float4 v = *(float4*)(buf + row * 128 + tx * 4);
        float ssq = v.x * v.x + v.y * v.y + v.z * v.z + v.w * v.w;
#pragma unroll
        for (int o = 16; o > 0; o >>= 1) ssq += __shfl_xor_sync(0xffffffffu, ssq, o);
        float inv = 1.0f / fmaxf(sqrtf(ssq), 1e-12f);
        v.x *= inv; v.y *= inv; v.z *= inv; v.w *= inv;
        if (act) {
            v.x = (v.x >= 0.f) ? v.x : 0.01f * v.x;
            v.y = (v.y >= 0.f) ? v.y : 0.01f * v.y;
            v.z = (v.z >= 0.f) ? v.z : 0.01f * v.z;
            v.w = (v.w >= 0.f) ? v.w : 0.01f * v.w;
        }
        *(float4*)(out + (size_t)(row0 + row) * D + tx * 4) = v;
    }
}

// ---------------- output linear: out = x@W + b, fused column-max pooling ---------
__global__ __launch_bounds__(256) void out_gemm_k(
    const float* __restrict__ x, const float* __restrict__ W, const float* __restrict__ b,
    float* __restrict__ out, int M, unsigned int* __restrict__ pool)
{
    __shared__ float buf[8192];
    __shared__ float bs[D];
    float* Xs = buf;
    float* Ws = buf + 2048;

    int t  = threadIdx.x;
    int tx = t & 31, ty = t >> 5;
    int row0 = blockIdx.x * 64;

    if (t < D) bs[t] = b[t];

    float acc[8][4];
#pragma unroll
    for (int i = 0; i < 8; i++)
#pragma unroll
        for (int j = 0; j < 4; j++) acc[i][j] = 0.f;

    for (int c = 0; c < 4; c++) {
        int kofs = c * 32;
        __syncthreads();
        {
            int r  = t >> 3;
            int c4 = (t & 7) * 4;
#pragma unroll
            for (int h = 0; h < 2; h++) {
                int row = r + h * 32;
                float4 v = make_float4(0.f, 0.f, 0.f, 0.f);
                if (row0 + row < M)
                    v = *(const float4*)(x + (size_t)(row0 + row) * D + kofs + c4);
                *(float4*)(Xs + row * 32 + c4) = v;
            }
#pragma unroll
            for (int h = 0; h < 4; h++) {
                int idx = t + h * 256;
                int wr = idx >> 5, wc = (idx & 31) * 4;
                *(float4*)(Ws + wr * 128 + wc) =
                    *(const float4*)(W + (size_t)(kofs + wr) * D + wc);
            }
        }
        __syncthreads();
#pragma unroll
        for (int kk = 0; kk < 32; kk++) {
            float a[8];
#pragma unroll
            for (int i = 0; i < 8; i++) a[i] = Xs[(ty * 8 + i) * 32 + kk];
            float4 bv = *(float4*)(Ws + kk * 128 + tx * 4);
#pragma unroll
            for (int i = 0; i < 8; i++) {
                acc[i][0] += a[i] * bv.x;
                acc[i][1] += a[i] * bv.y;
                acc[i][2] += a[i] * bv.z;
                acc[i][3] += a[i] * bv.w;
            }
        }
    }
    __syncthreads();

#pragma unroll
    for (int i = 0; i < 8; i++) {
        int row = ty * 8 + i;
        float4 o;
        o.x = acc[i][0] + bs[tx * 4 + 0];
        o.y = acc[i][1] + bs[tx * 4 + 1];
        o.z = acc[i][2] + bs[tx * 4 + 2];
        o.w = acc[i][3] + bs[tx * 4 + 3];
        *(float4*)(buf + row * 128 + tx * 4) = o;
        if (row0 + row < M)
            *(float4*)(out + (size_t)(row0 + row) * D + tx * 4) = o;
    }
    __syncthreads();

    // per-block column max -> one monotonic-uint atomicMax per column
    if (t < D) {
        int rmax = M - row0;
        if (rmax > 64) rmax = 64;
        float m = -3.402823466e38f;
        for (int r = 0; r < rmax; r++) m = fmaxf(m, buf[r * 128 + t]);
        unsigned u = __float_as_uint(m);
        unsigned mono = (u & 0x80000000u) ? ~u : (u | 0x80000000u);
        atomicMax(&pool[t], mono);
    }
}

__global__ void pool_combine_k(const unsigned int* __restrict__ pool, float* __restrict__ out)
{
    int t = threadIdx.x;  // 128
    unsigned a = pool[t], bmono = pool[t + D];
    float fa = __uint_as_float((a & 0x80000000u) ? (a & 0x7fffffffu) : ~a);
    float fb = __uint_as_float((bmono & 0x80000000u) ? (bmono & 0x7fffffffu) : ~bmono);
    out[t] = fa + fb;
}

// ---------------------------------- launch ---------------------------------------
extern "C" void kernel_launch(void* const* d_in, const int* in_sizes, int n_in,
                              void* d_out, int out_size)
{
    const float* nf_in = (const float*)d_in[0];
    const float* ef_in = (const float*)d_in[1];
    const float* nWc = (const float*)d_in[2];
    const float* nbc = (const float*)d_in[3];
    const float* nWn = (const float*)d_in[4];
    const float* nbn = (const float*)d_in[5];
    const float* nWe = (const float*)d_in[6];
    const float* nbe = (const float*)d_in[7];
    const float* eWc = (const float*)d_in[8];
    const float* ebc = (const float*)d_in[9];
    const float* eWn = (const float*)d_in[10];
    const float* ebn = (const float*)d_in[11];
    const float* eWe = (const float*)d_in[12];
    const float* ebe = (const float*)d_in[13];
    const float* Wno = (const float*)d_in[14];
    const float* bno = (const float*)d_in[15];
    const float* Weo = (const float*)d_in[16];
    const float* beo = (const float*)d_in[17];
    const int* ei  = (const int*)d_in[18];   // [2, E]
    const int* lei = (const int*)d_in[19];   // [2, L]
    const int* nei = (const int*)d_in[20];   // [E]
    const int* nes = (const int*)d_in[21];   // [E]
    const int* eni = (const int*)d_in[22];   // [L]
    const int* ens = (const int*)d_in[23];   // [L]
    float* outp = (float*)d_out;             // [pooled(128) | tn(N*128) | te(E*128)]

    float *nf0, *nf1, *ef0, *ef1, *an, *a1n, *ae, *a1e;
    unsigned int* pool;
    cudaGetSymbolAddress((void**)&nf0, g_nf0);
    cudaGetSymbolAddress((void**)&nf1, g_nf1);
    cudaGetSymbolAddress((void**)&ef0, g_ef0);
    cudaGetSymbolAddress((void**)&ef1, g_ef1);
    cudaGetSymbolAddress((void**)&an,  g_an);
    cudaGetSymbolAddress((void**)&a1n, g_a1n);
    cudaGetSymbolAddress((void**)&ae,  g_ae);
    cudaGetSymbolAddress((void**)&a1e, g_a1e);
    cudaGetSymbolAddress((void**)&pool, g_pool);

    float* nf_bufs[2] = { nf0, nf1 };
    float* ef_bufs[2] = { ef0, ef1 };
    const size_t nbytes = (size_t)N_NODES * D * sizeof(float);
    const size_t ebytes = (size_t)N_EDGES * D * sizeof(float);

    const float* nf_cur = nf_in;
    const float* ef_cur = ef_in;

    const int SCAT_BLOCKS = 25000;          // 8 warps/blk, ~4 edges/warp grid-stride
    const int NGB = (N_NODES + 63) / 64;    // 782
    const int EGB = (N_EDGES + 63) / 64;    // 12500

    for (int i = 0; i < NL; i++) {
        float* nf_next = nf_bufs[i & 1];
        float* ef_next = ef_bufs[i & 1];
        int act = (i < NL - 1);

        cudaMemsetAsync(an,  0, nbytes, 0);
        cudaMemsetAsync(a1n, 0, nbytes, 0);
        cudaMemsetAsync(ae,  0, ebytes, 0);
        cudaMemsetAsync(a1e, 0, ebytes, 0);

        // node aggregation: segment_sum(nf[row] -> col), segment_sum(ef[nei] -> nes)
        scatter_add_k<<<SCAT_BLOCKS, 256>>>(nf_cur, an,  ei,  ei + N_EDGES, N_EDGES);
        scatter_add_k<<<SCAT_BLOCKS, 256>>>(ef_cur, a1n, nei, nes,          N_EDGES);
        sage_gemm_k<<<NGB, 256>>>(nf_cur, an, a1n,
                                  nWc + (size_t)i * D * D, nWn + (size_t)i * D * D,
                                  nWe + (size_t)i * D * D,
                                  nbc + i * D, nbn + i * D, nbe + i * D,
                                  nf_next, N_NODES, act);

        // edge aggregation uses OLD nf (temp): nf_cur still points at it
        scatter_add_k<<<SCAT_BLOCKS, 256>>>(ef_cur, ae,  lei, lei + N_LINE, N_LINE);
        scatter_add_k<<<SCAT_BLOCKS, 256>>>(nf_cur, a1e, eni, ens,          N_LINE);
        sage_gemm_k<<<EGB, 256>>>(ef_cur, ae, a1e,
                                  eWc + (size_t)i * D * D, eWn + (size_t)i * D * D,
                                  eWe + (size_t)i * D * D,
                                  ebc + i * D, ebn + i * D, ebe + i * D,
                                  ef_next, N_EDGES, act);

        nf_cur = nf_next;
        ef_cur = ef_next;
    }

    cudaMemsetAsync(pool, 0, 2 * D * sizeof(unsigned int), 0);
    out_gemm_k<<<NGB, 256>>>(nf_cur, Wno, bno, outp + D, N_NODES, pool);
    out_gemm_k<<<EGB, 256>>>(ef_cur, Weo, beo, outp + D + (size_t)N_NODES * D, N_EDGES, pool + D);
    pool_combine_k<<<1, 128>>>(pool, outp);
}

// round 5
// speedup vs baseline: 1.1706x; 1.1706x over previous
#include <cuda_runtime.h>
#include <cstdint>
#include <cstddef>

#define N_NODES 50000
#define N_EDGES 800000
#define N_LINE  800000
#define D 128
#define NL 3

// ---------------- scratch (static device globals; no allocations) ----------------
__device__ float g_nf0[(size_t)N_NODES * D];
__device__ float g_nf1[(size_t)N_NODES * D];
__device__ float g_ef0[(size_t)N_EDGES * D];
__device__ float g_ef1[(size_t)N_EDGES * D];
__device__ float g_an [(size_t)N_NODES * D];
__device__ float g_a1n[(size_t)N_NODES * D];
__device__ float g_ae [(size_t)N_EDGES * D];
__device__ float g_a1e[(size_t)N_EDGES * D];
__device__ unsigned int g_pool[2 * D];

// ---------------- gather + scatter-add (one warp per edge-row, float4 RED) -------
__global__ void scatter_add_k(const float* __restrict__ src, float* __restrict__ dst,
                              const int* __restrict__ gidx, const int* __restrict__ sidx,
                              int count)
{
    int lane  = threadIdx.x & 31;
    int warp  = (blockIdx.x * blockDim.x + threadIdx.x) >> 5;
    int nwarp = (gridDim.x * blockDim.x) >> 5;
    for (int e = warp; e < count; e += nwarp) {
        int g = gidx[e];
        int s = sidx[e];
        float4 v = *((const float4*)(src + (size_t)g * D) + lane);
        atomicAdd((float4*)(dst + (size_t)s * D) + lane, v);
    }
}

// ============================ TF32 mma.sync helpers ==============================
__device__ __forceinline__ uint32_t f2tf32(float a) {
    uint32_t r;
    asm("cvt.rna.tf32.f32 %0, %1;" : "=r"(r) : "f"(a));
    return r;
}

__device__ __forceinline__ void mma8(float* d, uint32_t a0, uint32_t a1, uint32_t a2,
                                     uint32_t a3, uint32_t b0, uint32_t b1)
{
    asm volatile(
        "mma.sync.aligned.m16n8k8.row.col.f32.tf32.tf32.f32 "
        "{%0,%1,%2,%3}, {%4,%5,%6,%7}, {%8,%9}, {%0,%1,%2,%3};"
        : "+f"(d[0]), "+f"(d[1]), "+f"(d[2]), "+f"(d[3])
        : "r"(a0), "r"(a1), "r"(a2), "r"(a3), "r"(b0), "r"(b1));
}

// SMEM layout (dynamic, 76800 B total):
//   [0..512)        bias
//   [512..1024)     inv-norm
//   [1024..)        AsH 128x40 f (20480) | AsL (20480) | BsH 32x136 f (17408) | BsL (17408)
//   staging (128x132 f = 67584) aliases the tile region after the K loop.
#define SM_TOTAL 76800
#define A_STRIDE 40
#define B_STRIDE 136

// ============= TF32x3 tensor-core GEMM, fused bias / L2-norm / leaky / pool ======
// out[128 x 128] tile per CTA; K = nsrc*128 streamed in 32-wide chunks from up to
// 3 (x, W) pairs; fp32 accumulation in registers via 3-way tf32 split.
__global__ void __launch_bounds__(256, 2) tc_gemm_k(
    const float* __restrict__ x0, const float* __restrict__ x1, const float* __restrict__ x2,
    const float* __restrict__ W0, const float* __restrict__ W1, const float* __restrict__ W2,
    const float* __restrict__ b0, const float* __restrict__ b1, const float* __restrict__ b2,
    float* __restrict__ out, int M, int nsrc, int donorm, int act,
    unsigned int* __restrict__ pool)
{
    extern __shared__ char smem[];
    float* bias_s = (float*)smem;
    float* inv_s  = (float*)(smem + 512);
    float* AsH = (float*)(smem + 1024);
    float* AsL = AsH + 128 * A_STRIDE;                 // +5120 floats
    float* BsH = (float*)(smem + 1024 + 40960);
    float* BsL = BsH + 32 * B_STRIDE;                  // +4352 floats

    int t = threadIdx.x;
    int lane = t & 31, wid = t >> 5;
    int warpm = wid >> 2, warpn = wid & 3;             // 2 x 4 warp grid
    int gid = lane >> 2, tig = lane & 3;
    int row0 = blockIdx.x * 128;

    if (t < D) {
        float bb = b0[t];
        if (nsrc == 3) bb += b1[t] + b2[t];
        bias_s[t] = bb;
    }

    float acc[4][4][4];
#pragma unroll
    for (int i = 0; i < 4; i++)
#pragma unroll
        for (int j = 0; j < 4; j++)
#pragma unroll
            for (int k = 0; k < 4; k++) acc[i][j][k] = 0.f;

    const float* xs[3] = { x0, x1, x2 };
    const float* ws[3] = { W0, W1, W2 };
    const int nch = nsrc * 4;

    for (int c = 0; c < nch; c++) {
        const float* src = xs[c >> 2];
        const float* w   = ws[c >> 2];
        int kofs = (c & 3) * 32;

        __syncthreads();
        // ---- A tile: 128 x 32 fp32 -> hi/lo tf32 (row-major, stride 40) --------
#pragma unroll
        for (int h = 0; h < 4; h++) {
            int idx = t + h * 256;             // 1024 float4 slots
            int r = idx >> 3, cg = (idx & 7) * 4;
            float4 v = make_float4(0.f, 0.f, 0.f, 0.f);
            if (row0 + r < M)
                v = *(const float4*)(src + (size_t)(row0 + r) * D + kofs + cg);
            uint32_t hx = f2tf32(v.x), hy = f2tf32(v.y), hz = f2tf32(v.z), hw = f2tf32(v.w);
            float4 hi, lo;
            hi.x = __uint_as_float(hx); hi.y = __uint_as_float(hy);
            hi.z = __uint_as_float(hz); hi.w = __uint_as_float(hw);
            lo.x = __uint_as_float(f2tf32(v.x - hi.x));
            lo.y = __uint_as_float(f2tf32(v.y - hi.y));
            lo.z = __uint_as_float(f2tf32(v.z - hi.z));
            lo.w = __uint_as_float(f2tf32(v.w - hi.w));
            *(float4*)(AsH + r * A_STRIDE + cg) = hi;
            *(float4*)(AsL + r * A_STRIDE + cg) = lo;
        }
        // ---- B tile: W[kofs+k][n] 32 x 128 -> hi/lo tf32 (k-major, stride 136) --
#pragma unroll
        for (int h = 0; h < 4; h++) {
            int idx = t + h * 256;
            int k = idx >> 5, n4 = (idx & 31) * 4;
            float4 v = *(const float4*)(w + (size_t)(kofs + k) * D + n4);
            uint32_t hx = f2tf32(v.x), hy = f2tf32(v.y), hz = f2tf32(v.z), hw = f2tf32(v.w);
            float4 hi, lo;
            hi.x = __uint_as_float(hx); hi.y = __uint_as_float(hy);
            hi.z = __uint_as_float(hz); hi.w = __uint_as_float(hw);
            lo.x = __uint_as_float(f2tf32(v.x - hi.x));
            lo.y = __uint_as_float(f2tf32(v.y - hi.y));
            lo.z = __uint_as_float(f2tf32(v.z - hi.z));
            lo.w = __uint_as_float(f2tf32(v.w - hi.w));
            *(float4*)(BsH + k * B_STRIDE + n4) = hi;
            *(float4*)(BsL + k * B_STRIDE + n4) = lo;
        }
        __syncthreads();

        // ---- 4 k-steps of m16n8k8 with 3-way split (hh, hl, lh) ---------------
#pragma unroll
        for (int ks = 0; ks < 4; ks++) {
            int k = ks * 8 + tig;
            uint32_t ah[4][4], al[4][4];
#pragma unroll
            for (int mf = 0; mf < 4; mf++) {
                int base = (warpm * 64 + mf * 16 + gid) * A_STRIDE + k;
                ah[mf][0] = __float_as_uint(AsH[base]);
                ah[mf][1] = __float_as_uint(AsH[base + 8 * A_STRIDE]);
                ah[mf][2] = __float_as_uint(AsH[base + 4]);
                ah[mf][3] = __float_as_uint(AsH[base + 8 * A_STRIDE + 4]);
                al[mf][0] = __float_as_uint(AsL[base]);
                al[mf][1] = __float_as_uint(AsL[base + 8 * A_STRIDE]);
                al[mf][2] = __float_as_uint(AsL[base + 4]);
                al[mf][3] = __float_as_uint(AsL[base + 8 * A_STRIDE + 4]);
            }
#pragma unroll
            for (int nf = 0; nf < 4; nf++) {
                int bbase = k * B_STRIDE + warpn * 32 + nf * 8 + gid;
                uint32_t bh0 = __float_as_uint(BsH[bbase]);
                uint32_t bh1 = __float_as_uint(BsH[bbase + 4 * B_STRIDE]);
                uint32_t bl0 = __float_as_uint(BsL[bbase]);
                uint32_t bl1 = __float_as_uint(BsL[bbase + 4 * B_STRIDE]);
#pragma unroll
                for (int mf = 0; mf < 4; mf++) {
                    mma8(acc[mf][nf], ah[mf][0], ah[mf][1], ah[mf][2], ah[mf][3], bh0, bh1);
                    mma8(acc[mf][nf], ah[mf][0], ah[mf][1], ah[mf][2], ah[mf][3], bl0, bl1);
                    mma8(acc[mf][nf], al[mf][0], al[mf][1], al[mf][2], al[mf][3], bh0, bh1);
                }
            }
        }
    }
    __syncthreads();

    // ---- epilogue: stage acc + bias into smem (aliases operand tiles) ----------
    float* stg = (float*)(smem + 1024);                // 128 x 132 floats
#pragma unroll
    for (int mf = 0; mf < 4; mf++) {
        int row = warpm * 64 + mf * 16 + gid;
#pragma unroll
        for (int nf = 0; nf < 4; nf++) {
            int col = warpn * 32 + nf * 8 + 2 * tig;
            stg[row * 132 + col]           = acc[mf][nf][0] + bias_s[col];
            stg[row * 132 + col + 1]       = acc[mf][nf][1] + bias_s[col + 1];
            stg[(row + 8) * 132 + col]     = acc[mf][nf][2] + bias_s[col];
            stg[(row + 8) * 132 + col + 1] = acc[mf][nf][3] + bias_s[col + 1];
        }
    }
    __syncthreads();

    // ---- pass1: per-row inverse L2 norm ----------------------------------------
    if (donorm && t < 128) {
        float ssq = 0.f;
#pragma unroll
        for (int j = 0; j < 32; j++) {
            float4 v = *(float4*)(stg + t * 132 + j * 4);
            ssq += v.x * v.x + v.y * v.y + v.z * v.z + v.w * v.w;
        }
        inv_s[t] = 1.0f / fmaxf(sqrtf(ssq), 1e-12f);
    }
    __syncthreads();

    // ---- pass2: normalize/act, coalesced store, fused column max-pool ----------
    int s = t & 31;
    float4 pmax = make_float4(-3.402823466e38f, -3.402823466e38f,
                              -3.402823466e38f, -3.402823466e38f);
#pragma unroll
    for (int h = 0; h < 16; h++) {
        int idx = t + h * 256;
        int row = idx >> 5;                    // col group == s (256 % 32 == 0)
        float4 v = *(float4*)(stg + row * 132 + s * 4);
        if (donorm) {
            float iv = inv_s[row];
            v.x *= iv; v.y *= iv; v.z *= iv; v.w *= iv;
            if (act) {
                v.x = (v.x >= 0.f) ? v.x : 0.01f * v.x;
                v.y = (v.y >= 0.f) ? v.y : 0.01f * v.y;
                v.z = (v.z >= 0.f) ? v.z : 0.01f * v.z;
                v.w = (v.w >= 0.f) ? v.w : 0.01f * v.w;
            }
        }
        if (row0 + row < M) {
            *(float4*)(out + (size_t)(row0 + row) * D + s * 4) = v;
            if (pool) {
                pmax.x = fmaxf(pmax.x, v.x); pmax.y = fmaxf(pmax.y, v.y);
                pmax.z = fmaxf(pmax.z, v.z); pmax.w = fmaxf(pmax.w, v.w);
            }
        }
    }
    if (pool) {
        float pv[4] = { pmax.x, pmax.y, pmax.z, pmax.w };
#pragma unroll
        for (int j = 0; j < 4; j++) {
            unsigned u = __float_as_uint(pv[j]);
            unsigned mono = (u & 0x80000000u) ? ~u : (u | 0x80000000u);
            atomicMax(&pool[s * 4 + j], mono);
        }
    }
}

__global__ void pool_combine_k(const unsigned int* __restrict__ pool, float* __restrict__ out)
{
    int t = threadIdx.x;  // 128
    unsigned a = pool[t], bmono = pool[t + D];
    float fa = __uint_as_float((a & 0x80000000u) ? (a & 0x7fffffffu) : ~a);
    float fb = __uint_as_float((bmono & 0x80000000u) ? (bmono & 0x7fffffffu) : ~bmono);
    out[t] = fa + fb;
}

// ---------------------------------- launch ---------------------------------------
extern "C" void kernel_launch(void* const* d_in, const int* in_sizes, int n_in,
                              void* d_out, int out_size)
{
    const float* nf_in = (const float*)d_in[0];
    const float* ef_in = (const float*)d_in[1];
    const float* nWc = (const float*)d_in[2];
    const float* nbc = (const float*)d_in[3];
    const float* nWn = (const float*)d_in[4];
    const float* nbn = (const float*)d_in[5];
    const float* nWe = (const float*)d_in[6];
    const float* nbe = (const float*)d_in[7];
    const float* eWc = (const float*)d_in[8];
    const float* ebc = (const float*)d_in[9];
    const float* eWn = (const float*)d_in[10];
    const float* ebn = (const float*)d_in[11];
    const float* eWe = (const float*)d_in[12];
    const float* ebe = (const float*)d_in[13];
    const float* Wno = (const float*)d_in[14];
    const float* bno = (const float*)d_in[15];
    const float* Weo = (const float*)d_in[16];
    const float* beo = (const float*)d_in[17];
    const int* ei  = (const int*)d_in[18];   // [2, E]
    const int* lei = (const int*)d_in[19];   // [2, L]
    const int* nei = (const int*)d_in[20];   // [E]
    const int* nes = (const int*)d_in[21];   // [E]
    const int* eni = (const int*)d_in[22];   // [L]
    const int* ens = (const int*)d_in[23];   // [L]
    float* outp = (float*)d_out;             // [pooled(128) | tn(N*128) | te(E*128)]

    cudaFuncSetAttribute(tc_gemm_k, cudaFuncAttributeMaxDynamicSharedMemorySize, SM_TOTAL);

    float *nf0, *nf1, *ef0, *ef1, *an, *a1n, *ae, *a1e;
    unsigned int* pool;
    cudaGetSymbolAddress((void**)&nf0, g_nf0);
    cudaGetSymbolAddress((void**)&nf1, g_nf1);
    cudaGetSymbolAddress((void**)&ef0, g_ef0);
    cudaGetSymbolAddress((void**)&ef1, g_ef1);
    cudaGetSymbolAddress((void**)&an,  g_an);
    cudaGetSymbolAddress((void**)&a1n, g_a1n);
    cudaGetSymbolAddress((void**)&ae,  g_ae);
    cudaGetSymbolAddress((void**)&a1e, g_a1e);
    cudaGetSymbolAddress((void**)&pool, g_pool);

    float* nf_bufs[2] = { nf0, nf1 };
    float* ef_bufs[2] = { ef0, ef1 };
    const size_t nbytes = (size_t)N_NODES * D * sizeof(float);
    const size_t ebytes = (size_t)N_EDGES * D * sizeof(float);

    const float* nf_cur = nf_in;
    const float* ef_cur = ef_in;

    const int SCAT_BLOCKS = 25000;
    const int NGB = (N_NODES + 127) / 128;   // 391
    const int EGB = (N_EDGES + 127) / 128;   // 6250

    for (int i = 0; i < NL; i++) {
        float* nf_next = nf_bufs[i & 1];
        float* ef_next = ef_bufs[i & 1];
        int act = (i < NL - 1);

        cudaMemsetAsync(an,  0, nbytes, 0);
        cudaMemsetAsync(a1n, 0, nbytes, 0);
        cudaMemsetAsync(ae,  0, ebytes, 0);
        cudaMemsetAsync(a1e, 0, ebytes, 0);

        // node aggregation
        scatter_add_k<<<SCAT_BLOCKS, 256>>>(nf_cur, an,  ei,  ei + N_EDGES, N_EDGES);
        scatter_add_k<<<SCAT_BLOCKS, 256>>>(ef_cur, a1n, nei, nes,          N_EDGES);
        tc_gemm_k<<<NGB, 256, SM_TOTAL>>>(nf_cur, an, a1n,
                                          nWc + (size_t)i * D * D, nWn + (size_t)i * D * D,
                                          nWe + (size_t)i * D * D,
                                          nbc + i * D, nbn + i * D, nbe + i * D,
                                          nf_next, N_NODES, 3, 1, act, nullptr);

        // edge aggregation (uses OLD nf: nf_cur still points at it)
        scatter_add_k<<<SCAT_BLOCKS, 256>>>(ef_cur, ae,  lei, lei + N_LINE, N_LINE);
        scatter_add_k<<<SCAT_BLOCKS, 256>>>(nf_cur, a1e, eni, ens,          N_LINE);
        tc_gemm_k<<<EGB, 256, SM_TOTAL>>>(ef_cur, ae, a1e,
                                          eWc + (size_t)i * D * D, eWn + (size_t)i * D * D,
                                          eWe + (size_t)i * D * D,
                                          ebc + i * D, ebn + i * D, ebe + i * D,
                                          ef_next, N_EDGES, 3, 1, act, nullptr);

        nf_cur = nf_next;
        ef_cur = ef_next;
    }

    cudaMemsetAsync(pool, 0, 2 * D * sizeof(unsigned int), 0);
    tc_gemm_k<<<NGB, 256, SM_TOTAL>>>(nf_cur, nullptr, nullptr,
                                      Wno, nullptr, nullptr,
                                      bno, nullptr, nullptr,
                                      outp + D, N_NODES, 1, 0, 0, pool);
    tc_gemm_k<<<EGB, 256, SM_TOTAL>>>(ef_cur, nullptr, nullptr,
                                      Weo, nullptr, nullptr,
                                      beo, nullptr, nullptr,
                                      outp + D + (size_t)N_NODES * D, N_EDGES, 1, 0, 0, pool + D);
    pool_combine_k<<<1, 128>>>(pool, outp);
}

// round 6
// speedup vs baseline: 1.3719x; 1.1720x over previous
#include <cuda_runtime.h>
#include <cstdint>
#include <cstddef>

#define N_NODES 50000
#define N_EDGES 800000
#define N_LINE  800000
#define D 128
#define NL 3

// ---------------- scratch (static device globals; no allocations) ----------------
__device__ float g_nf0[(size_t)N_NODES * D];
__device__ float g_nf1[(size_t)N_NODES * D];
__device__ float g_ef0[(size_t)N_EDGES * D];
__device__ float g_ef1[(size_t)N_EDGES * D];
__device__ float g_an [(size_t)N_NODES * D];
__device__ float g_a1n[(size_t)N_NODES * D];
__device__ float g_ae [(size_t)N_EDGES * D];
__device__ float g_a1e[(size_t)N_EDGES * D];
__device__ unsigned int g_pool[2 * D];
// packed weights: 20 matrices x [hi 128x64 u32 | lo 128x64 u32]
__device__ uint32_t g_wpk[20 * 16384];

// ---------------- gather + scatter-add (one warp per edge-row, float4 RED) -------
__global__ void scatter_add_k(const float* __restrict__ src, float* __restrict__ dst,
                              const int* __restrict__ gidx, const int* __restrict__ sidx,
                              int count)
{
    int lane  = threadIdx.x & 31;
    int warp  = (blockIdx.x * blockDim.x + threadIdx.x) >> 5;
    int nwarp = (gridDim.x * blockDim.x) >> 5;
    for (int e = warp; e < count; e += nwarp) {
        int g = gidx[e];
        int s = sidx[e];
        float4 v = *((const float4*)(src + (size_t)g * D) + lane);
        atomicAdd((float4*)(dst + (size_t)s * D) + lane, v);
    }
}

// ============================ bf16 split helpers =================================
__device__ __forceinline__ uint32_t packbf(float hi_el, float lo_el) {
    // result: high 16 bits = bf16(hi_el), low 16 bits = bf16(lo_el)
    uint32_t r;
    asm("cvt.rn.bf16x2.f32 %0, %1, %2;" : "=r"(r) : "f"(hi_el), "f"(lo_el));
    return r;
}
__device__ __forceinline__ float bf_lo(uint32_t u) { return __uint_as_float(u << 16); }
__device__ __forceinline__ float bf_hi(uint32_t u) { return __uint_as_float(u & 0xFFFF0000u); }

__device__ __forceinline__ void mma16(float* d, uint32_t a0, uint32_t a1, uint32_t a2,
                                      uint32_t a3, uint32_t b0, uint32_t b1)
{
    asm volatile(
        "mma.sync.aligned.m16n8k16.row.col.f32.bf16.bf16.f32 "
        "{%0,%1,%2,%3}, {%4,%5,%6,%7}, {%8,%9}, {%0,%1,%2,%3};"
        : "+f"(d[0]), "+f"(d[1]), "+f"(d[2]), "+f"(d[3])
        : "r"(a0), "r"(a1), "r"(a2), "r"(a3), "r"(b0), "r"(b1));
}

// ---------------- weight pre-pack: W[k][n] fp32 -> hi/lo planes [n][k2] ----------
__global__ void wprep_k(const float* __restrict__ W, uint32_t* __restrict__ out, int nmats)
{
    int i = blockIdx.x * blockDim.x + threadIdx.x;
    if (i >= nmats * 8192) return;
    int m = i >> 13, r = i & 8191;
    int n = r >> 6, k2 = r & 63;
    const float* w = W + (size_t)m * 16384;
    float x0 = w[(2 * k2) * D + n];
    float x1 = w[(2 * k2 + 1) * D + n];
    uint32_t hi = packbf(x1, x0);
    float r0 = x0 - bf_lo(hi);
    float r1 = x1 - bf_hi(hi);
    uint32_t lo = packbf(r1, r0);
    out[(size_t)m * 16384 + n * 64 + k2]        = hi;
    out[(size_t)m * 16384 + 8192 + n * 64 + k2] = lo;
}

// SMEM layout (dynamic, 68608 B):
//   [0..512)   bias  [512..1024) inv-norm
//   [1024..)   AsH 128x20 u32 (10240) | AsL (10240) | BsH 128x20 u32 (10240) | BsL
//   staging 128x132 f (67584) aliases the tile region after the K loop.
#define SM_TOTAL 68608
#define AST 20
#define BST 20

// ========== bf16x3 tensor-core GEMM, fused bias / L2-norm / leaky / pool =========
__global__ void __launch_bounds__(256, 2) tc_gemm_k(
    const float* __restrict__ x0, const float* __restrict__ x1, const float* __restrict__ x2,
    const uint32_t* __restrict__ pk0, const uint32_t* __restrict__ pk1,
    const uint32_t* __restrict__ pk2,
    const float* __restrict__ b0, const float* __restrict__ b1, const float* __restrict__ b2,
    float* __restrict__ out, int M, int nsrc, int donorm, int act,
    unsigned int* __restrict__ pool)
{
    extern __shared__ char smem[];
    float* bias_s = (float*)smem;
    float* inv_s  = (float*)(smem + 512);
    uint32_t* AsH = (uint32_t*)(smem + 1024);
    uint32_t* AsL = AsH + 128 * AST;
    uint32_t* BsH = AsL + 128 * AST;
    uint32_t* BsL = BsH + 128 * BST;

    int t = threadIdx.x;
    int lane = t & 31, wid = t >> 5;
    int warpm = wid >> 2, warpn = wid & 3;             // 2 x 4 warp grid
    int gid = lane >> 2, tig = lane & 3;
    int row0 = blockIdx.x * 128;

    if (t < D) {
        float bb = b0[t];
        if (nsrc == 3) bb += b1[t] + b2[t];
        bias_s[t] = bb;
    }

    float acc[4][4][4];
#pragma unroll
    for (int i = 0; i < 4; i++)
#pragma unroll
        for (int j = 0; j < 4; j++)
#pragma unroll
            for (int k = 0; k < 4; k++) acc[i][j][k] = 0.f;

    const float* xs[3] = { x0, x1, x2 };
    const uint32_t* ps[3] = { pk0, pk1, pk2 };
    const int nch = nsrc * 4;

    for (int c = 0; c < nch; c++) {
        const float* src = xs[c >> 2];
        const uint32_t* pk = ps[c >> 2];
        int cc = c & 3;
        int kofs = cc * 32;                  // float-k offset
        int k2o  = cc * 16;                  // packed-pair offset

        __syncthreads();
        // ---- A tile: 128 x 32 fp32 -> packed bf16 hi/lo pairs ------------------
#pragma unroll
        for (int h = 0; h < 4; h++) {
            int idx = t + h * 256;           // 1024 float4 slots
            int r = idx >> 3, j = idx & 7;   // j: float4 within row (k2 pair j*2)
            float4 v = make_float4(0.f, 0.f, 0.f, 0.f);
            if (row0 + r < M)
                v = *(const float4*)(src + (size_t)(row0 + r) * D + kofs + j * 4);
            uint32_t h0 = packbf(v.y, v.x);
            uint32_t h1 = packbf(v.w, v.z);
            float r0 = v.x - bf_lo(h0), r1 = v.y - bf_hi(h0);
            float r2 = v.z - bf_lo(h1), r3 = v.w - bf_hi(h1);
            uint32_t l0 = packbf(r1, r0);
            uint32_t l1 = packbf(r3, r2);
            *(uint2*)(AsH + r * AST + j * 2) = make_uint2(h0, h1);
            *(uint2*)(AsL + r * AST + j * 2) = make_uint2(l0, l1);
        }
        // ---- B tile: straight copy of pre-packed planes ------------------------
        {
            const uint32_t* bh = pk;
            const uint32_t* bl = pk + 8192;
#pragma unroll
            for (int h = 0; h < 2; h++) {
                int idx = t + h * 256;       // 512 uint4 slots
                int n = idx >> 2, g = (idx & 3) * 4;
                *(uint4*)(BsH + n * BST + g) = *(const uint4*)(bh + n * 64 + k2o + g);
                *(uint4*)(BsL + n * BST + g) = *(const uint4*)(bl + n * 64 + k2o + g);
            }
        }
        __syncthreads();

        // ---- 2 k-steps of m16n8k16 with 3-way split (hh, hl, lh) ---------------
#pragma unroll
        for (int ks = 0; ks < 2; ks++) {
            int kb = ks * 8;
            uint32_t bh[4][2], bl[4][2];
#pragma unroll
            for (int nf = 0; nf < 4; nf++) {
                int nb = (warpn * 32 + nf * 8 + gid) * BST + kb + tig;
                bh[nf][0] = BsH[nb]; bh[nf][1] = BsH[nb + 4];
                bl[nf][0] = BsL[nb]; bl[nf][1] = BsL[nb + 4];
            }
#pragma unroll
            for (int mf = 0; mf < 4; mf++) {
                int ab = (warpm * 64 + mf * 16 + gid) * AST + kb + tig;
                uint32_t ah0 = AsH[ab],           ah1 = AsH[ab + 8 * AST];
                uint32_t ah2 = AsH[ab + 4],       ah3 = AsH[ab + 8 * AST + 4];
                uint32_t al0 = AsL[ab],           al1 = AsL[ab + 8 * AST];
                uint32_t al2 = AsL[ab + 4],       al3 = AsL[ab + 8 * AST + 4];
#pragma unroll
                for (int nf = 0; nf < 4; nf++) {
                    mma16(acc[mf][nf], ah0, ah1, ah2, ah3, bh[nf][0], bh[nf][1]);
                    mma16(acc[mf][nf], ah0, ah1, ah2, ah3, bl[nf][0], bl[nf][1]);
                    mma16(acc[mf][nf], al0, al1, al2, al3, bh[nf][0], bh[nf][1]);
                }
            }
        }
    }
    __syncthreads();

    // ---- epilogue: stage acc + bias into smem (aliases operand tiles) ----------
    float* stg = (float*)(smem + 1024);                // 128 x 132 floats
#pragma unroll
    for (int mf = 0; mf < 4; mf++) {
        int row = warpm * 64 + mf * 16 + gid;
#pragma unroll
        for (int nf = 0; nf < 4; nf++) {
            int col = warpn * 32 + nf * 8 + 2 * tig;
            stg[row * 132 + col]           = acc[mf][nf][0] + bias_s[col];
            stg[row * 132 + col + 1]       = acc[mf][nf][1] + bias_s[col + 1];
            stg[(row + 8) * 132 + col]     = acc[mf][nf][2] + bias_s[col];
            stg[(row + 8) * 132 + col + 1] = acc[mf][nf][3] + bias_s[col + 1];
        }
    }
    __syncthreads();

    // ---- pass1: per-row inverse L2 norm ----------------------------------------
    if (donorm && t < 128) {
        float ssq = 0.f;
#pragma unroll
        for (int j = 0; j < 32; j++) {
            float4 v = *(float4*)(stg + t * 132 + j * 4);
            ssq += v.x * v.x + v.y * v.y + v.z * v.z + v.w * v.w;
        }
        inv_s[t] = 1.0f / fmaxf(sqrtf(ssq), 1e-12f);
    }
    __syncthreads();

    // ---- pass2: normalize/act, coalesced store, fused column max-pool ----------
    int s = t & 31;
    float4 pmax = make_float4(-3.402823466e38f, -3.402823466e38f,
                              -3.402823466e38f, -3.402823466e38f);
#pragma unroll
    for (int h = 0; h < 16; h++) {
        int idx = t + h * 256;
        int row = idx >> 5;
        float4 v = *(float4*)(stg + row * 132 + s * 4);
        if (donorm) {
            float iv = inv_s[row];
            v.x *= iv; v.y *= iv; v.z *= iv; v.w *= iv;
            if (act) {
                v.x = (v.x >= 0.f) ? v.x : 0.01f * v.x;
                v.y = (v.y >= 0.f) ? v.y : 0.01f * v.y;
                v.z = (v.z >= 0.f) ? v.z : 0.01f * v.z;
                v.w = (v.w >= 0.f) ? v.w : 0.01f * v.w;
            }
        }
        if (row0 + row < M) {
            *(float4*)(out + (size_t)(row0 + row) * D + s * 4) = v;
            if (pool) {
                pmax.x = fmaxf(pmax.x, v.x); pmax.y = fmaxf(pmax.y, v.y);
                pmax.z = fmaxf(pmax.z, v.z); pmax.w = fmaxf(pmax.w, v.w);
            }
        }
    }
    if (pool) {
        float pv[4] = { pmax.x, pmax.y, pmax.z, pmax.w };
#pragma unroll
        for (int j = 0; j < 4; j++) {
            unsigned u = __float_as_uint(pv[j]);
            unsigned mono = (u & 0x80000000u) ? ~u : (u | 0x80000000u);
            atomicMax(&pool[s * 4 + j], mono);
        }
    }
}

__global__ void pool_combine_k(const unsigned int* __restrict__ pool, float* __restrict__ out)
{
    int t = threadIdx.x;  // 128
    unsigned a = pool[t], bmono = pool[t + D];
    float fa = __uint_as_float((a & 0x80000000u) ? (a & 0x7fffffffu) : ~a);
    float fb = __uint_as_float((bmono & 0x80000000u) ? (bmono & 0x7fffffffu) : ~bmono);
    out[t] = fa + fb;
}

// ---------------------------------- launch ---------------------------------------
extern "C" void kernel_launch(void* const* d_in, const int* in_sizes, int n_in,
                              void* d_out, int out_size)
{
    const float* nf_in = (const float*)d_in[0];
    const float* ef_in = (const float*)d_in[1];
    const float* nWc = (const float*)d_in[2];
    const float* nbc = (const float*)d_in[3];
    const float* nWn = (const float*)d_in[4];
    const float* nbn = (const float*)d_in[5];
    const float* nWe = (const float*)d_in[6];
    const float* nbe = (const float*)d_in[7];
    const float* eWc = (const float*)d_in[8];
    const float* ebc = (const float*)d_in[9];
    const float* eWn = (const float*)d_in[10];
    const float* ebn = (const float*)d_in[11];
    const float* eWe = (const float*)d_in[12];
    const float* ebe = (const float*)d_in[13];
    const float* Wno = (const float*)d_in[14];
    const float* bno = (const float*)d_in[15];
    const float* Weo = (const float*)d_in[16];
    const float* beo = (const float*)d_in[17];
    const int* ei  = (const int*)d_in[18];   // [2, E]
    const int* lei = (const int*)d_in[19];   // [2, L]
    const int* nei = (const int*)d_in[20];   // [E]
    const int* nes = (const int*)d_in[21];   // [E]
    const int* eni = (const int*)d_in[22];   // [L]
    const int* ens = (const int*)d_in[23];   // [L]
    float* outp = (float*)d_out;             // [pooled(128) | tn(N*128) | te(E*128)]

    cudaFuncSetAttribute(tc_gemm_k, cudaFuncAttributeMaxDynamicSharedMemorySize, SM_TOTAL);

    float *nf0, *nf1, *ef0, *ef1, *an, *a1n, *ae, *a1e;
    unsigned int* pool;
    uint32_t* wpk;
    cudaGetSymbolAddress((void**)&nf0, g_nf0);
    cudaGetSymbolAddress((void**)&nf1, g_nf1);
    cudaGetSymbolAddress((void**)&ef0, g_ef0);
    cudaGetSymbolAddress((void**)&ef1, g_ef1);
    cudaGetSymbolAddress((void**)&an,  g_an);
    cudaGetSymbolAddress((void**)&a1n, g_a1n);
    cudaGetSymbolAddress((void**)&ae,  g_ae);
    cudaGetSymbolAddress((void**)&a1e, g_a1e);
    cudaGetSymbolAddress((void**)&pool, g_pool);
    cudaGetSymbolAddress((void**)&wpk, g_wpk);

    // ---- pre-pack weights: slots 0-8 node (c,n,e x3 layers), 9-17 edge, 18/19 out
    wprep_k<<<(3 * 8192 + 255) / 256, 256>>>(nWc, wpk + (size_t)0  * 16384, 3);
    wprep_k<<<(3 * 8192 + 255) / 256, 256>>>(nWn, wpk + (size_t)3  * 16384, 3);
    wprep_k<<<(3 * 8192 + 255) / 256, 256>>>(nWe, wpk + (size_t)6  * 16384, 3);
    wprep_k<<<(3 * 8192 + 255) / 256, 256>>>(eWc, wpk + (size_t)9  * 16384, 3);
    wprep_k<<<(3 * 8192 + 255) / 256, 256>>>(eWn, wpk + (size_t)12 * 16384, 3);
    wprep_k<<<(3 * 8192 + 255) / 256, 256>>>(eWe, wpk + (size_t)15 * 16384, 3);
    wprep_k<<<(8192 + 255) / 256, 256>>>(Wno, wpk + (size_t)18 * 16384, 1);
    wprep_k<<<(8192 + 255) / 256, 256>>>(Weo, wpk + (size_t)19 * 16384, 1);

    float* nf_bufs[2] = { nf0, nf1 };
    float* ef_bufs[2] = { ef0, ef1 };
    const size_t nbytes = (size_t)N_NODES * D * sizeof(float);
    const size_t ebytes = (size_t)N_EDGES * D * sizeof(float);

    const float* nf_cur = nf_in;
    const float* ef_cur = ef_in;

    const int SCAT_BLOCKS = 25000;
    const int NGB = (N_NODES + 127) / 128;   // 391
    const int EGB = (N_EDGES + 127) / 128;   // 6250

    for (int i = 0; i < NL; i++) {
        float* nf_next = nf_bufs[i & 1];
        float* ef_next = ef_bufs[i & 1];
        int act = (i < NL - 1);

        cudaMemsetAsync(an,  0, nbytes, 0);
        cudaMemsetAsync(a1n, 0, nbytes, 0);
        cudaMemsetAsync(ae,  0, ebytes, 0);
        cudaMemsetAsync(a1e, 0, ebytes, 0);

        // node aggregation
        scatter_add_k<<<SCAT_BLOCKS, 256>>>(nf_cur, an,  ei,  ei + N_EDGES, N_EDGES);
        scatter_add_k<<<SCAT_BLOCKS, 256>>>(ef_cur, a1n, nei, nes,          N_EDGES);
        tc_gemm_k<<<NGB, 256, SM_TOTAL>>>(nf_cur, an, a1n,
                                          wpk + (size_t)(0 + i) * 16384,
                                          wpk + (size_t)(3 + i) * 16384,
                                          wpk + (size_t)(6 + i) * 16384,
                                          nbc + i * D, nbn + i * D, nbe + i * D,
                                          nf_next, N_NODES, 3, 1, act, nullptr);

        // edge aggregation (uses OLD nf: nf_cur still points at it)
        scatter_add_k<<<SCAT_BLOCKS, 256>>>(ef_cur, ae,  lei, lei + N_LINE, N_LINE);
        scatter_add_k<<<SCAT_BLOCKS, 256>>>(nf_cur, a1e, eni, ens,          N_LINE);
        tc_gemm_k<<<EGB, 256, SM_TOTAL>>>(ef_cur, ae, a1e,
                                          wpk + (size_t)(9  + i) * 16384,
                                          wpk + (size_t)(12 + i) * 16384,
                                          wpk + (size_t)(15 + i) * 16384,
                                          ebc + i * D, ebn + i * D, ebe + i * D,
                                          ef_next, N_EDGES, 3, 1, act, nullptr);

        nf_cur = nf_next;
        ef_cur = ef_next;
    }

    cudaMemsetAsync(pool, 0, 2 * D * sizeof(unsigned int), 0);
    tc_gemm_k<<<NGB, 256, SM_TOTAL>>>(nf_cur, nullptr, nullptr,
                                      wpk + (size_t)18 * 16384, nullptr, nullptr,
                                      bno, nullptr, nullptr,
                                      outp + D, N_NODES, 1, 0, 0, pool);
    tc_gemm_k<<<EGB, 256, SM_TOTAL>>>(ef_cur, nullptr, nullptr,
                                      wpk + (size_t)19 * 16384, nullptr, nullptr,
                                      beo, nullptr, nullptr,
                                      outp + D + (size_t)N_NODES * D, N_EDGES, 1, 0, 0, pool + D);
    pool_combine_k<<<1, 128>>>(pool, outp);
}

// round 7
// speedup vs baseline: 1.8778x; 1.3688x over previous
#include <cuda_runtime.h>
#include <cstdint>
#include <cstddef>

#define N_NODES 50000
#define N_EDGES 800000
#define N_LINE  800000
#define D 128
#define NL 3

// ---------------- scratch (static device globals; no allocations) ----------------
__device__ float g_nf0[(size_t)N_NODES * D];
__device__ float g_nf1[(size_t)N_NODES * D];
__device__ float g_ef0[(size_t)N_EDGES * D];
__device__ float g_ef1[(size_t)N_EDGES * D];
__device__ float g_an [(size_t)N_NODES * D];
__device__ float g_a1n[(size_t)N_NODES * D];
__device__ float g_ae [(size_t)N_EDGES * D];
__device__ float g_a1e[(size_t)N_EDGES * D];
__device__ unsigned int g_pool[2 * D];
// packed weights: 20 matrices x [hi 128x64 u32 | lo 128x64 u32]
__device__ uint32_t g_wpk[20 * 16384];

// ---------------- gather + scatter-add (one warp per edge-row, float4 RED) -------
__global__ void scatter_add_k(const float* __restrict__ src, float* __restrict__ dst,
                              const int* __restrict__ gidx, const int* __restrict__ sidx,
                              int count)
{
    int lane  = threadIdx.x & 31;
    int warp  = (blockIdx.x * blockDim.x + threadIdx.x) >> 5;
    int nwarp = (gridDim.x * blockDim.x) >> 5;
    for (int e = warp; e < count; e += nwarp) {
        int g = gidx[e];
        int s = sidx[e];
        float4 v = *((const float4*)(src + (size_t)g * D) + lane);
        atomicAdd((float4*)(dst + (size_t)s * D) + lane, v);
    }
}

// ============================ bf16 split helpers =================================
__device__ __forceinline__ uint32_t packbf(float hi_el, float lo_el) {
    uint32_t r;
    asm("cvt.rn.bf16x2.f32 %0, %1, %2;" : "=r"(r) : "f"(hi_el), "f"(lo_el));
    return r;
}
__device__ __forceinline__ float bf_lo(uint32_t u) { return __uint_as_float(u << 16); }
__device__ __forceinline__ float bf_hi(uint32_t u) { return __uint_as_float(u & 0xFFFF0000u); }

__device__ __forceinline__ void mma16(float* d, uint32_t a0, uint32_t a1, uint32_t a2,
                                      uint32_t a3, uint32_t b0, uint32_t b1)
{
    asm volatile(
        "mma.sync.aligned.m16n8k16.row.col.f32.bf16.bf16.f32 "
        "{%0,%1,%2,%3}, {%4,%5,%6,%7}, {%8,%9}, {%0,%1,%2,%3};"
        : "+f"(d[0]), "+f"(d[1]), "+f"(d[2]), "+f"(d[3])
        : "r"(a0), "r"(a1), "r"(a2), "r"(a3), "r"(b0), "r"(b1));
}

__device__ __forceinline__ void ldm4(uint32_t* r, uint32_t addr) {
    asm volatile("ldmatrix.sync.aligned.m8n8.x4.shared.b16 {%0,%1,%2,%3}, [%4];"
                 : "=r"(r[0]), "=r"(r[1]), "=r"(r[2]), "=r"(r[3]) : "r"(addr));
}
__device__ __forceinline__ void cp16(uint32_t dst, const void* src) {
    asm volatile("cp.async.ca.shared.global [%0], [%1], 16;" :: "r"(dst), "l"(src));
}
#define CP_COMMIT() asm volatile("cp.async.commit_group;" ::: "memory")
#define CP_WAIT0()  asm volatile("cp.async.wait_group 0;" ::: "memory")

// ---------------- weight pre-pack: W[k][n] fp32 -> hi/lo planes [n][k2] ----------
__global__ void wprep_k(const float* __restrict__ W, uint32_t* __restrict__ out, int nmats)
{
    int i = blockIdx.x * blockDim.x + threadIdx.x;
    if (i >= nmats * 8192) return;
    int m = i >> 13, r = i & 8191;
    int n = r >> 6, k2 = r & 63;
    const float* w = W + (size_t)m * 16384;
    float x0 = w[(2 * k2) * D + n];
    float x1 = w[(2 * k2 + 1) * D + n];
    uint32_t hi = packbf(x1, x0);
    float r0 = x0 - bf_lo(hi);
    float r1 = x1 - bf_hi(hi);
    uint32_t lo = packbf(r1, r0);
    out[(size_t)m * 16384 + n * 64 + k2]        = hi;
    out[(size_t)m * 16384 + 8192 + n * 64 + k2] = lo;
}

// SMEM (dynamic, 82944 B):
//   [0..512) bias, [512..1024) inv
//   [1024..) two 40960B stages: AsH 128x20u32 | AsL | BsH 128x20u32 | BsL
//   epilogue staging 128x132 f (67584 B) aliases the stage region.
#define SM_TOTAL 82944
#define STG_BYTES 40960

// ========== bf16x3 tensor-core GEMM, cp.async + ldmatrix 2-stage pipeline ========
__global__ void __launch_bounds__(256, 2) tc_gemm_k(
    const float* __restrict__ x0, const float* __restrict__ x1, const float* __restrict__ x2,
    const uint32_t* __restrict__ pk0, const uint32_t* __restrict__ pk1,
    const uint32_t* __restrict__ pk2,
    const float* __restrict__ b0, const float* __restrict__ b1, const float* __restrict__ b2,
    float* __restrict__ out, int M, int nsrc, int donorm, int act,
    unsigned int* __restrict__ pool)
{
    extern __shared__ char smem[];
    float* bias_s = (float*)smem;
    float* inv_s  = (float*)(smem + 512);
    uint32_t stiles = (uint32_t)__cvta_generic_to_shared(smem) + 1024;

    int t = threadIdx.x;
    int lane = t & 31, wid = t >> 5;
    int warpm = wid >> 2, warpn = wid & 3;
    int gid = lane >> 2, tig = lane & 3;
    int row0 = blockIdx.x * 128;

    if (t < D) {
        float bb = b0[t];
        if (nsrc == 3) bb += b1[t] + b2[t];
        bias_s[t] = bb;
    }

    // thread-constant ldmatrix byte offsets (stride 20 u32 = 80 B per row)
    int arow = warpm * 64 + (lane & 7) + ((lane >> 3) & 1) * 8;
    uint32_t aoff = (uint32_t)(arow * 80) + (lane >> 4) * 16;
    int nrow = warpn * 32 + (lane & 7) + (lane >> 4) * 8;
    uint32_t boff = (uint32_t)(nrow * 80) + ((lane >> 3) & 1) * 16;

    // A loader mapping: 4 float4 per thread
    int ar = t >> 3;        // rows ar, ar+32, ar+64, ar+96
    int aj = t & 7;         // float4 index within 32-float row

    float acc[4][4][4];
#pragma unroll
    for (int i = 0; i < 4; i++)
#pragma unroll
        for (int j = 0; j < 4; j++)
#pragma unroll
            for (int k = 0; k < 4; k++) acc[i][j][k] = 0.f;

    const float* xs[3] = { x0, x1, x2 };
    const uint32_t* ps[3] = { pk0, pk1, pk2 };
    const int nch = nsrc * 4;

    float4 av[4];

    // ---- prologue: chunk 0 into stage 0 ----------------------------------------
    {
        const float* src = xs[0];
#pragma unroll
        for (int h = 0; h < 4; h++) {
            int r = ar + h * 32;
            av[h] = make_float4(0.f, 0.f, 0.f, 0.f);
            if (row0 + r < M)
                av[h] = *(const float4*)(src + (size_t)(row0 + r) * D + aj * 4);
        }
        const uint32_t* sH = ps[0];
        const uint32_t* sL = ps[0] + 8192;
        uint32_t dH = stiles + 20480, dL = stiles + 30720;
#pragma unroll
        for (int i = 0; i < 2; i++) {
            int idx = t + i * 256;
            int n = idx >> 2, j4 = idx & 3;
            cp16(dH + n * 80 + j4 * 16, sH + n * 64 + j4 * 4);
            cp16(dL + n * 80 + j4 * 16, sL + n * 64 + j4 * 4);
        }
        CP_COMMIT();
        uint32_t* pH = (uint32_t*)(smem + 1024);
        uint32_t* pL = (uint32_t*)(smem + 1024 + 10240);
#pragma unroll
        for (int h = 0; h < 4; h++) {
            int r = ar + h * 32;
            float4 v = av[h];
            uint32_t h0 = packbf(v.y, v.x), h1 = packbf(v.w, v.z);
            float r0 = v.x - bf_lo(h0), r1 = v.y - bf_hi(h0);
            float r2 = v.z - bf_lo(h1), r3 = v.w - bf_hi(h1);
            *(uint2*)(pH + r * 20 + aj * 2) = make_uint2(h0, h1);
            *(uint2*)(pL + r * 20 + aj * 2) = make_uint2(packbf(r1, r0), packbf(r3, r2));
        }
        CP_WAIT0();
    }
    __syncthreads();

    // ---- main pipelined loop ----------------------------------------------------
    for (int c = 0; c < nch; c++) {
        int s = c & 1;
        int have_next = (c + 1 < nch);

        if (have_next) {
            int c1 = c + 1;
            const float* src = xs[c1 >> 2];
            int kofs = (c1 & 3) * 32;
#pragma unroll
            for (int h = 0; h < 4; h++) {
                int r = ar + h * 32;
                av[h] = make_float4(0.f, 0.f, 0.f, 0.f);
                if (row0 + r < M)
                    av[h] = *(const float4*)(src + (size_t)(row0 + r) * D + kofs + aj * 4);
            }
            const uint32_t* pk = ps[c1 >> 2];
            int k2o = (c1 & 3) * 16;
            const uint32_t* sH = pk + k2o;
            const uint32_t* sL = pk + 8192 + k2o;
            uint32_t sb = stiles + (s ^ 1) * STG_BYTES;
            uint32_t dH = sb + 20480, dL = sb + 30720;
#pragma unroll
            for (int i = 0; i < 2; i++) {
                int idx = t + i * 256;
                int n = idx >> 2, j4 = idx & 3;
                cp16(dH + n * 80 + j4 * 16, sH + n * 64 + j4 * 4);
                cp16(dL + n * 80 + j4 * 16, sL + n * 64 + j4 * 4);
            }
            CP_COMMIT();
        }

        // ---- MMA on stage s via ldmatrix ----------------------------------------
        {
            uint32_t bAH = stiles + s * STG_BYTES;
            uint32_t bAL = bAH + 10240;
            uint32_t bBH = bAH + 20480;
            uint32_t bBL = bAH + 30720;
#pragma unroll
            for (int ks = 0; ks < 2; ks++) {
                uint32_t kso = ks * 32;
                uint32_t bh[4][2], bl[4][2], r4[4];
#pragma unroll
                for (int p = 0; p < 2; p++) {
                    ldm4(r4, bBH + boff + p * 1280 + kso);
                    bh[2 * p][0] = r4[0]; bh[2 * p][1] = r4[1];
                    bh[2 * p + 1][0] = r4[2]; bh[2 * p + 1][1] = r4[3];
                    ldm4(r4, bBL + boff + p * 1280 + kso);
                    bl[2 * p][0] = r4[0]; bl[2 * p][1] = r4[1];
                    bl[2 * p + 1][0] = r4[2]; bl[2 * p + 1][1] = r4[3];
                }
#pragma unroll
                for (int mf = 0; mf < 4; mf++) {
                    uint32_t ah[4], al[4];
                    ldm4(ah, bAH + aoff + mf * 1280 + kso);
                    ldm4(al, bAL + aoff + mf * 1280 + kso);
#pragma unroll
                    for (int nf = 0; nf < 4; nf++) {
                        mma16(acc[mf][nf], ah[0], ah[1], ah[2], ah[3], bh[nf][0], bh[nf][1]);
                        mma16(acc[mf][nf], ah[0], ah[1], ah[2], ah[3], bl[nf][0], bl[nf][1]);
                        mma16(acc[mf][nf], al[0], al[1], al[2], al[3], bh[nf][0], bh[nf][1]);
                    }
                }
            }
        }

        if (have_next) {
            uint32_t* pH = (uint32_t*)(smem + 1024 + (s ^ 1) * STG_BYTES);
            uint32_t* pL = pH + 2560;
#pragma unroll
            for (int h = 0; h < 4; h++) {
                int r = ar + h * 32;
                float4 v = av[h];
                uint32_t h0 = packbf(v.y, v.x), h1 = packbf(v.w, v.z);
                float r0 = v.x - bf_lo(h0), r1 = v.y - bf_hi(h0);
                float r2 = v.z - bf_lo(h1), r3 = v.w - bf_hi(h1);
                *(uint2*)(pH + r * 20 + aj * 2) = make_uint2(h0, h1);
                *(uint2*)(pL + r * 20 + aj * 2) = make_uint2(packbf(r1, r0), packbf(r3, r2));
            }
            CP_WAIT0();
        }
        __syncthreads();
    }

    // ---- epilogue: stage acc + bias into smem (aliases operand tiles) ----------
    float* stg = (float*)(smem + 1024);                // 128 x 132 floats
#pragma unroll
    for (int mf = 0; mf < 4; mf++) {
        int row = warpm * 64 + mf * 16 + gid;
#pragma unroll
        for (int nf = 0; nf < 4; nf++) {
            int col = warpn * 32 + nf * 8 + 2 * tig;
            stg[row * 132 + col]           = acc[mf][nf][0] + bias_s[col];
            stg[row * 132 + col + 1]       = acc[mf][nf][1] + bias_s[col + 1];
            stg[(row + 8) * 132 + col]     = acc[mf][nf][2] + bias_s[col];
            stg[(row + 8) * 132 + col + 1] = acc[mf][nf][3] + bias_s[col + 1];
        }
    }
    __syncthreads();

    // ---- pass1: per-row inverse L2 norm ----------------------------------------
    if (donorm && t < 128) {
        float ssq = 0.f;
#pragma unroll
        for (int j = 0; j < 32; j++) {
            float4 v = *(float4*)(stg + t * 132 + j * 4);
            ssq += v.x * v.x + v.y * v.y + v.z * v.z + v.w * v.w;
        }
        inv_s[t] = 1.0f / fmaxf(sqrtf(ssq), 1e-12f);
    }
    __syncthreads();

    // ---- pass2: normalize/act, coalesced store, fused column max-pool ----------
    int s = t & 31;
    float4 pmax = make_float4(-3.402823466e38f, -3.402823466e38f,
                              -3.402823466e38f, -3.402823466e38f);
#pragma unroll
    for (int h = 0; h < 16; h++) {
        int idx = t + h * 256;
        int row = idx >> 5;
        float4 v = *(float4*)(stg + row * 132 + s * 4);
        if (donorm) {
            float iv = inv_s[row];
            v.x *= iv; v.y *= iv; v.z *= iv; v.w *= iv;
            if (act) {
                v.x = (v.x >= 0.f) ? v.x : 0.01f * v.x;
                v.y = (v.y >= 0.f) ? v.y : 0.01f * v.y;
                v.z = (v.z >= 0.f) ? v.z : 0.01f * v.z;
                v.w = (v.w >= 0.f) ? v.w : 0.01f * v.w;
            }
        }
        if (row0 + row < M) {
            *(float4*)(out + (size_t)(row0 + row) * D + s * 4) = v;
            if (pool) {
                pmax.x = fmaxf(pmax.x, v.x); pmax.y = fmaxf(pmax.y, v.y);
                pmax.z = fmaxf(pmax.z, v.z); pmax.w = fmaxf(pmax.w, v.w);
            }
        }
    }
    if (pool) {
        float pv[4] = { pmax.x, pmax.y, pmax.z, pmax.w };
#pragma unroll
        for (int j = 0; j < 4; j++) {
            unsigned u = __float_as_uint(pv[j]);
            unsigned mono = (u & 0x80000000u) ? ~u : (u | 0x80000000u);
            atomicMax(&pool[s * 4 + j], mono);
        }
    }
}

__global__ void pool_combine_k(const unsigned int* __restrict__ pool, float* __restrict__ out)
{
    int t = threadIdx.x;  // 128
    unsigned a = pool[t], bmono = pool[t + D];
    float fa = __uint_as_float((a & 0x80000000u) ? (a & 0x7fffffffu) : ~a);
    float fb = __uint_as_float((bmono & 0x80000000u) ? (bmono & 0x7fffffffu) : ~bmono);
    out[t] = fa + fb;
}

// ---------------------------------- launch ---------------------------------------
extern "C" void kernel_launch(void* const* d_in, const int* in_sizes, int n_in,
                              void* d_out, int out_size)
{
    const float* nf_in = (const float*)d_in[0];
    const float* ef_in = (const float*)d_in[1];
    const float* nWc = (const float*)d_in[2];
    const float* nbc = (const float*)d_in[3];
    const float* nWn = (const float*)d_in[4];
    const float* nbn = (const float*)d_in[5];
    const float* nWe = (const float*)d_in[6];
    const float* nbe = (const float*)d_in[7];
    const float* eWc = (const float*)d_in[8];
    const float* ebc = (const float*)d_in[9];
    const float* eWn = (const float*)d_in[10];
    const float* ebn = (const float*)d_in[11];
    const float* eWe = (const float*)d_in[12];
    const float* ebe = (const float*)d_in[13];
    const float* Wno = (const float*)d_in[14];
    const float* bno = (const float*)d_in[15];
    const float* Weo = (const float*)d_in[16];
    const float* beo = (const float*)d_in[17];
    const int* ei  = (const int*)d_in[18];   // [2, E]
    const int* lei = (const int*)d_in[19];   // [2, L]
    const int* nei = (const int*)d_in[20];   // [E]
    const int* nes = (const int*)d_in[21];   // [E]
    const int* eni = (const int*)d_in[22];   // [L]
    const int* ens = (const int*)d_in[23];   // [L]
    float* outp = (float*)d_out;             // [pooled(128) | tn(N*128) | te(E*128)]

    cudaFuncSetAttribute(tc_gemm_k, cudaFuncAttributeMaxDynamicSharedMemorySize, SM_TOTAL);

    float *nf0, *nf1, *ef0, *ef1, *an, *a1n, *ae, *a1e;
    unsigned int* pool;
    uint32_t* wpk;
    cudaGetSymbolAddress((void**)&nf0, g_nf0);
    cudaGetSymbolAddress((void**)&nf1, g_nf1);
    cudaGetSymbolAddress((void**)&ef0, g_ef0);
    cudaGetSymbolAddress((void**)&ef1, g_ef1);
    cudaGetSymbolAddress((void**)&an,  g_an);
    cudaGetSymbolAddress((void**)&a1n, g_a1n);
    cudaGetSymbolAddress((void**)&ae,  g_ae);
    cudaGetSymbolAddress((void**)&a1e, g_a1e);
    cudaGetSymbolAddress((void**)&pool, g_pool);
    cudaGetSymbolAddress((void**)&wpk, g_wpk);

    // ---- pre-pack weights: slots 0-8 node (c,n,e x3 layers), 9-17 edge, 18/19 out
    wprep_k<<<(3 * 8192 + 255) / 256, 256>>>(nWc, wpk + (size_t)0  * 16384, 3);
    wprep_k<<<(3 * 8192 + 255) / 256, 256>>>(nWn, wpk + (size_t)3  * 16384, 3);
    wprep_k<<<(3 * 8192 + 255) / 256, 256>>>(nWe, wpk + (size_t)6  * 16384, 3);
    wprep_k<<<(3 * 8192 + 255) / 256, 256>>>(eWc, wpk + (size_t)9  * 16384, 3);
    wprep_k<<<(3 * 8192 + 255) / 256, 256>>>(eWn, wpk + (size_t)12 * 16384, 3);
    wprep_k<<<(3 * 8192 + 255) / 256, 256>>>(eWe, wpk + (size_t)15 * 16384, 3);
    wprep_k<<<(8192 + 255) / 256, 256>>>(Wno, wpk + (size_t)18 * 16384, 1);
    wprep_k<<<(8192 + 255) / 256, 256>>>(Weo, wpk + (size_t)19 * 16384, 1);

    float* nf_bufs[2] = { nf0, nf1 };
    float* ef_bufs[2] = { ef0, ef1 };
    const size_t nbytes = (size_t)N_NODES * D * sizeof(float);
    const size_t ebytes = (size_t)N_EDGES * D * sizeof(float);

    const float* nf_cur = nf_in;
    const float* ef_cur = ef_in;

    const int SCAT_BLOCKS = 25000;
    const int NGB = (N_NODES + 127) / 128;   // 391
    const int EGB = (N_EDGES + 127) / 128;   // 6250

    for (int i = 0; i < NL; i++) {
        float* nf_next = nf_bufs[i & 1];
        float* ef_next = ef_bufs[i & 1];
        int act = (i < NL - 1);

        cudaMemsetAsync(an,  0, nbytes, 0);
        cudaMemsetAsync(a1n, 0, nbytes, 0);
        cudaMemsetAsync(ae,  0, ebytes, 0);
        cudaMemsetAsync(a1e, 0, ebytes, 0);

        // node aggregation
        scatter_add_k<<<SCAT_BLOCKS, 256>>>(nf_cur, an,  ei,  ei + N_EDGES, N_EDGES);
        scatter_add_k<<<SCAT_BLOCKS, 256>>>(ef_cur, a1n, nei, nes,          N_EDGES);
        tc_gemm_k<<<NGB, 256, SM_TOTAL>>>(nf_cur, an, a1n,
                                          wpk + (size_t)(0 + i) * 16384,
                                          wpk + (size_t)(3 + i) * 16384,
                                          wpk + (size_t)(6 + i) * 16384,
                                          nbc + i * D, nbn + i * D, nbe + i * D,
                                          nf_next, N_NODES, 3, 1, act, nullptr);

        // edge aggregation (uses OLD nf: nf_cur still points at it)
        scatter_add_k<<<SCAT_BLOCKS, 256>>>(ef_cur, ae,  lei, lei + N_LINE, N_LINE);
        scatter_add_k<<<SCAT_BLOCKS, 256>>>(nf_cur, a1e, eni, ens,          N_LINE);
        tc_gemm_k<<<EGB, 256, SM_TOTAL>>>(ef_cur, ae, a1e,
                                          wpk + (size_t)(9  + i) * 16384,
                                          wpk + (size_t)(12 + i) * 16384,
                                          wpk + (size_t)(15 + i) * 16384,
                                          ebc + i * D, ebn + i * D, ebe + i * D,
                                          ef_next, N_EDGES, 3, 1, act, nullptr);

        nf_cur = nf_next;
        ef_cur = ef_next;
    }

    cudaMemsetAsync(pool, 0, 2 * D * sizeof(unsigned int), 0);
    tc_gemm_k<<<NGB, 256, SM_TOTAL>>>(nf_cur, nullptr, nullptr,
                                      wpk + (size_t)18 * 16384, nullptr, nullptr,
                                      bno, nullptr, nullptr,
                                      outp + D, N_NODES, 1, 0, 0, pool);
    tc_gemm_k<<<EGB, 256, SM_TOTAL>>>(ef_cur, nullptr, nullptr,
                                      wpk + (size_t)19 * 16384, nullptr, nullptr,
                                      beo, nullptr, nullptr,
                                      outp + D + (size_t)N_NODES * D, N_EDGES, 1, 0, 0, pool + D);
    pool_combine_k<<<1, 128>>>(pool, outp);
}

// round 8
// speedup vs baseline: 1.9491x; 1.0380x over previous
#include <cuda_runtime.h>
#include <cstdint>
#include <cstddef>

#define N_NODES 50000
#define N_EDGES 800000
#define N_LINE  800000
#define D 128
#define NL 3

// ---------------- scratch (static device globals; no allocations) ----------------
__device__ float g_nf0[(size_t)N_NODES * D];
__device__ float g_nf1[(size_t)N_NODES * D];
__device__ float g_ef0[(size_t)N_EDGES * D];
__device__ float g_ef1[(size_t)N_EDGES * D];
__device__ float g_an [(size_t)N_NODES * D];   // zero at entry/exit of every call
__device__ float g_a1n[(size_t)N_NODES * D];
__device__ float g_ae [(size_t)N_EDGES * D];
__device__ float g_a1e[(size_t)N_EDGES * D];
__device__ unsigned int g_pool[2 * D];
// packed weights: 20 matrices x [hi 128x64 u32 | lo 128x64 u32]
__device__ uint32_t g_wpk[20 * 16384];

// ---------------- gather + scatter-add (one warp per edge-row, float4 RED) -------
__global__ void scatter_add_k(const float* __restrict__ src, float* __restrict__ dst,
                              const int* __restrict__ gidx, const int* __restrict__ sidx,
                              int count)
{
    int lane  = threadIdx.x & 31;
    int warp  = (blockIdx.x * blockDim.x + threadIdx.x) >> 5;
    int nwarp = (gridDim.x * blockDim.x) >> 5;
    for (int e = warp; e < count; e += nwarp) {
        int g = gidx[e];
        int s = sidx[e];
        float4 v = *((const float4*)(src + (size_t)g * D) + lane);
        atomicAdd((float4*)(dst + (size_t)s * D) + lane, v);
    }
}

// ============================ bf16 split helpers =================================
__device__ __forceinline__ uint32_t packbf(float hi_el, float lo_el) {
    uint32_t r;
    asm("cvt.rn.bf16x2.f32 %0, %1, %2;" : "=r"(r) : "f"(hi_el), "f"(lo_el));
    return r;
}
__device__ __forceinline__ float bf_lo(uint32_t u) { return __uint_as_float(u << 16); }
__device__ __forceinline__ float bf_hi(uint32_t u) { return __uint_as_float(u & 0xFFFF0000u); }

__device__ __forceinline__ void mma16(float* d, uint32_t a0, uint32_t a1, uint32_t a2,
                                      uint32_t a3, uint32_t b0, uint32_t b1)
{
    asm volatile(
        "mma.sync.aligned.m16n8k16.row.col.f32.bf16.bf16.f32 "
        "{%0,%1,%2,%3}, {%4,%5,%6,%7}, {%8,%9}, {%0,%1,%2,%3};"
        : "+f"(d[0]), "+f"(d[1]), "+f"(d[2]), "+f"(d[3])
        : "r"(a0), "r"(a1), "r"(a2), "r"(a3), "r"(b0), "r"(b1));
}

__device__ __forceinline__ void ldm4(uint32_t* r, uint32_t addr) {
    asm volatile("ldmatrix.sync.aligned.m8n8.x4.shared.b16 {%0,%1,%2,%3}, [%4];"
                 : "=r"(r[0]), "=r"(r[1]), "=r"(r[2]), "=r"(r[3]) : "r"(addr));
}
__device__ __forceinline__ void cp16(uint32_t dst, const void* src) {
    asm volatile("cp.async.ca.shared.global [%0], [%1], 16;" :: "r"(dst), "l"(src));
}
#define CP_COMMIT() asm volatile("cp.async.commit_group;" ::: "memory")
#define CP_WAIT0()  asm volatile("cp.async.wait_group 0;" ::: "memory")

// ---------------- weight pre-pack (single launch, all 20 matrices) ---------------
__global__ void wprep_all_k(const float* __restrict__ nWc, const float* __restrict__ nWn,
                            const float* __restrict__ nWe, const float* __restrict__ eWc,
                            const float* __restrict__ eWn, const float* __restrict__ eWe,
                            const float* __restrict__ Wno, const float* __restrict__ Weo,
                            uint32_t* __restrict__ out)
{
    int i = blockIdx.x * blockDim.x + threadIdx.x;
    if (i >= 20 * 8192) return;
    int m = i >> 13, r = i & 8191;
    int n = r >> 6, k2 = r & 63;
    const float* srcs[8] = { nWc, nWn, nWe, eWc, eWn, eWe, Wno, Weo };
    int grp = (m < 18) ? (m / 3) : (m - 18 + 6);
    int loc = (m < 18) ? (m % 3) : 0;
    const float* w = srcs[grp] + (size_t)loc * 16384;
    float x0 = w[(2 * k2) * D + n];
    float x1 = w[(2 * k2 + 1) * D + n];
    uint32_t hi = packbf(x1, x0);
    float r0 = x0 - bf_lo(hi);
    float r1 = x1 - bf_hi(hi);
    uint32_t lo = packbf(r1, r0);
    out[(size_t)m * 16384 + n * 64 + k2]        = hi;
    out[(size_t)m * 16384 + 8192 + n * 64 + k2] = lo;
}

// SMEM (dynamic, 82944 B):
//   [0..512) bias, [512..1024) inv
//   [1024..) two 40960B stages: AsH 128x20u32 | AsL | BsH 128x20u32 | BsL
//   epilogue staging 128x132 f (67584 B) aliases the stage region.
#define SM_TOTAL 82944
#define STG_BYTES 40960

// == combined bf16x3 tensor-core GEMM (node blocks + edge blocks in one grid) =====
// blocks [0, ngb) -> set A; blocks [ngb, ngb+egb) -> set B. nsrc==3 layer GEMMs
// additionally re-zero their consumed aggregation slices (replaces memsets).
__global__ void __launch_bounds__(256, 2) tc_gemm2_k(
    const float* Ax0, const float* Ax1, const float* Ax2,
    const uint32_t* Apk0, const uint32_t* Apk1, const uint32_t* Apk2,
    const float* Ab0, const float* Ab1, const float* Ab2,
    float* Aout, int AM, unsigned int* Apool,
    const float* Bx0, const float* Bx1, const float* Bx2,
    const uint32_t* Bpk0, const uint32_t* Bpk1, const uint32_t* Bpk2,
    const float* Bb0, const float* Bb1, const float* Bb2,
    float* Bout, int BM, unsigned int* Bpool,
    int ngb, int nsrc, int donorm, int act)
{
    extern __shared__ char smem[];
    float* bias_s = (float*)smem;
    float* inv_s  = (float*)(smem + 512);
    uint32_t stiles = (uint32_t)__cvta_generic_to_shared(smem) + 1024;

    int t = threadIdx.x;
    int lane = t & 31, wid = t >> 5;
    int warpm = wid >> 2, warpn = wid & 3;
    int gid = lane >> 2, tig = lane & 3;

    // -------- per-block param select --------
    const float *x0, *x1, *x2, *b0, *b1, *b2;
    const uint32_t *pk0, *pk1, *pk2;
    float* out;
    unsigned int* pool;
    int M, row0;
    if ((int)blockIdx.x < ngb) {
        x0 = Ax0; x1 = Ax1; x2 = Ax2; pk0 = Apk0; pk1 = Apk1; pk2 = Apk2;
        b0 = Ab0; b1 = Ab1; b2 = Ab2; out = Aout; M = AM; pool = Apool;
        row0 = blockIdx.x * 128;
    } else {
        x0 = Bx0; x1 = Bx1; x2 = Bx2; pk0 = Bpk0; pk1 = Bpk1; pk2 = Bpk2;
        b0 = Bb0; b1 = Bb1; b2 = Bb2; out = Bout; M = BM; pool = Bpool;
        row0 = (blockIdx.x - ngb) * 128;
    }

    if (t < D) {
        float bb = b0[t];
        if (nsrc == 3) bb += b1[t] + b2[t];
        bias_s[t] = bb;
    }

    // thread-constant ldmatrix byte offsets (stride 20 u32 = 80 B per row)
    int arow = warpm * 64 + (lane & 7) + ((lane >> 3) & 1) * 8;
    uint32_t aoff = (uint32_t)(arow * 80) + (lane >> 4) * 16;
    int nrow = warpn * 32 + (lane & 7) + (lane >> 4) * 8;
    uint32_t boff = (uint32_t)(nrow * 80) + ((lane >> 3) & 1) * 16;

    // A loader mapping: 4 float4 per thread
    int ar = t >> 3;        // rows ar, ar+32, ar+64, ar+96
    int aj = t & 7;         // float4 index within 32-float row

    float acc[4][4][4];
#pragma unroll
    for (int i = 0; i < 4; i++)
#pragma unroll
        for (int j = 0; j < 4; j++)
#pragma unroll
            for (int k = 0; k < 4; k++) acc[i][j][k] = 0.f;

    const float* xs[3] = { x0, x1, x2 };
    const uint32_t* ps[3] = { pk0, pk1, pk2 };
    const int nch = nsrc * 4;

    float4 av[4];

    // ---- prologue: chunk 0 into stage 0 ----------------------------------------
    {
        const float* src = xs[0];
#pragma unroll
        for (int h = 0; h < 4; h++) {
            int r = ar + h * 32;
            av[h] = make_float4(0.f, 0.f, 0.f, 0.f);
            if (row0 + r < M)
                av[h] = *(const float4*)(src + (size_t)(row0 + r) * D + aj * 4);
        }
        const uint32_t* sH = ps[0];
        const uint32_t* sL = ps[0] + 8192;
        uint32_t dH = stiles + 20480, dL = stiles + 30720;
#pragma unroll
        for (int i = 0; i < 2; i++) {
            int idx = t + i * 256;
            int n = idx >> 2, j4 = idx & 3;
            cp16(dH + n * 80 + j4 * 16, sH + n * 64 + j4 * 4);
            cp16(dL + n * 80 + j4 * 16, sL + n * 64 + j4 * 4);
        }
        CP_COMMIT();
        uint32_t* pH = (uint32_t*)(smem + 1024);
        uint32_t* pL = (uint32_t*)(smem + 1024 + 10240);
#pragma unroll
        for (int h = 0; h < 4; h++) {
            int r = ar + h * 32;
            float4 v = av[h];
            uint32_t h0 = packbf(v.y, v.x), h1 = packbf(v.w, v.z);
            float r0 = v.x - bf_lo(h0), r1 = v.y - bf_hi(h0);
            float r2 = v.z - bf_lo(h1), r3 = v.w - bf_hi(h1);
            *(uint2*)(pH + r * 20 + aj * 2) = make_uint2(h0, h1);
            *(uint2*)(pL + r * 20 + aj * 2) = make_uint2(packbf(r1, r0), packbf(r3, r2));
        }
        CP_WAIT0();
    }
    __syncthreads();

    // ---- main pipelined loop ----------------------------------------------------
    for (int c = 0; c < nch; c++) {
        int s = c & 1;
        int have_next = (c + 1 < nch);

        if (have_next) {
            int c1 = c + 1;
            const float* src = xs[c1 >> 2];
            int kofs = (c1 & 3) * 32;
#pragma unroll
            for (int h = 0; h < 4; h++) {
                int r = ar + h * 32;
                av[h] = make_float4(0.f, 0.f, 0.f, 0.f);
                if (row0 + r < M)
                    av[h] = *(const float4*)(src + (size_t)(row0 + r) * D + kofs + aj * 4);
            }
            const uint32_t* pk = ps[c1 >> 2];
            int k2o = (c1 & 3) * 16;
            const uint32_t* sH = pk + k2o;
            const uint32_t* sL = pk + 8192 + k2o;
            uint32_t sb = stiles + (s ^ 1) * STG_BYTES;
            uint32_t dH = sb + 20480, dL = sb + 30720;
#pragma unroll
            for (int i = 0; i < 2; i++) {
                int idx = t + i * 256;
                int n = idx >> 2, j4 = idx & 3;
                cp16(dH + n * 80 + j4 * 16, sH + n * 64 + j4 * 4);
                cp16(dL + n * 80 + j4 * 16, sL + n * 64 + j4 * 4);
            }
            CP_COMMIT();
        }

        // ---- MMA on stage s via ldmatrix ----------------------------------------
        {
            uint32_t bAH = stiles + s * STG_BYTES;
            uint32_t bAL = bAH + 10240;
            uint32_t bBH = bAH + 20480;
            uint32_t bBL = bAH + 30720;
#pragma unroll
            for (int ks = 0; ks < 2; ks++) {
                uint32_t kso = ks * 32;
                uint32_t bh[4][2], bl[4][2], r4[4];
#pragma unroll
                for (int p = 0; p < 2; p++) {
                    ldm4(r4, bBH + boff + p * 1280 + kso);
                    bh[2 * p][0] = r4[0]; bh[2 * p][1] = r4[1];
                    bh[2 * p + 1][0] = r4[2]; bh[2 * p + 1][1] = r4[3];
                    ldm4(r4, bBL + boff + p * 1280 + kso);
                    bl[2 * p][0] = r4[0]; bl[2 * p][1] = r4[1];
                    bl[2 * p + 1][0] = r4[2]; bl[2 * p + 1][1] = r4[3];
                }
#pragma unroll
                for (int mf = 0; mf < 4; mf++) {
                    uint32_t ah[4], al[4];
                    ldm4(ah, bAH + aoff + mf * 1280 + kso);
                    ldm4(al, bAL + aoff + mf * 1280 + kso);
#pragma unroll
                    for (int nf = 0; nf < 4; nf++) {
                        mma16(acc[mf][nf], ah[0], ah[1], ah[2], ah[3], bh[nf][0], bh[nf][1]);
                        mma16(acc[mf][nf], ah[0], ah[1], ah[2], ah[3], bl[nf][0], bl[nf][1]);
                        mma16(acc[mf][nf], al[0], al[1], al[2], al[3], bh[nf][0], bh[nf][1]);
                    }
                }
            }
        }

        if (have_next) {
            uint32_t* pH = (uint32_t*)(smem + 1024 + (s ^ 1) * STG_BYTES);
            uint32_t* pL = pH + 2560;
#pragma unroll
            for (int h = 0; h < 4; h++) {
                int r = ar + h * 32;
                float4 v = av[h];
                uint32_t h0 = packbf(v.y, v.x), h1 = packbf(v.w, v.z);
                float r0 = v.x - bf_lo(h0), r1 = v.y - bf_hi(h0);
                float r2 = v.z - bf_lo(h1), r3 = v.w - bf_hi(h1);
                *(uint2*)(pH + r * 20 + aj * 2) = make_uint2(h0, h1);
                *(uint2*)(pL + r * 20 + aj * 2) = make_uint2(packbf(r1, r0), packbf(r3, r2));
            }
            CP_WAIT0();
        }
        __syncthreads();
    }

    // ---- epilogue: stage acc + bias into smem (aliases operand tiles) ----------
    float* stg = (float*)(smem + 1024);                // 128 x 132 floats
#pragma unroll
    for (int mf = 0; mf < 4; mf++) {
        int row = warpm * 64 + mf * 16 + gid;
#pragma unroll
        for (int nf = 0; nf < 4; nf++) {
            int col = warpn * 32 + nf * 8 + 2 * tig;
            stg[row * 132 + col]           = acc[mf][nf][0] + bias_s[col];
            stg[row * 132 + col + 1]       = acc[mf][nf][1] + bias_s[col + 1];
            stg[(row + 8) * 132 + col]     = acc[mf][nf][2] + bias_s[col];
            stg[(row + 8) * 132 + col + 1] = acc[mf][nf][3] + bias_s[col + 1];
        }
    }
    __syncthreads();

    // ---- pass1: per-row inverse L2 norm ----------------------------------------
    if (donorm && t < 128) {
        float ssq = 0.f;
#pragma unroll
        for (int j = 0; j < 32; j++) {
            float4 v = *(float4*)(stg + t * 132 + j * 4);
            ssq += v.x * v.x + v.y * v.y + v.z * v.z + v.w * v.w;
        }
        inv_s[t] = 1.0f / fmaxf(sqrtf(ssq), 1e-12f);
    }
    __syncthreads();

    // ---- pass2: normalize/act, coalesced store, fused column max-pool ----------
    int s = t & 31;
    float4 pmax = make_float4(-3.402823466e38f, -3.402823466e38f,
                              -3.402823466e38f, -3.402823466e38f);
#pragma unroll
    for (int h = 0; h < 16; h++) {
        int idx = t + h * 256;
        int row = idx >> 5;
        float4 v = *(float4*)(stg + row * 132 + s * 4);
        if (donorm) {
            float iv = inv_s[row];
            v.x *= iv; v.y *= iv; v.z *= iv; v.w *= iv;
            if (act) {
                v.x = (v.x >= 0.f) ? v.x : 0.01f * v.x;
                v.y = (v.y >= 0.f) ? v.y : 0.01f * v.y;
                v.z = (v.z >= 0.f) ? v.z : 0.01f * v.z;
                v.w = (v.w >= 0.f) ? v.w : 0.01f * v.w;
            }
        }
        if (row0 + row < M) {
            *(float4*)(out + (size_t)(row0 + row) * D + s * 4) = v;
            if (pool) {
                pmax.x = fmaxf(pmax.x, v.x); pmax.y = fmaxf(pmax.y, v.y);
                pmax.z = fmaxf(pmax.z, v.z); pmax.w = fmaxf(pmax.w, v.w);
            }
        }
    }
    if (pool) {
        float pv[4] = { pmax.x, pmax.y, pmax.z, pmax.w };
#pragma unroll
        for (int j = 0; j < 4; j++) {
            unsigned u = __float_as_uint(pv[j]);
            unsigned mono = (u & 0x80000000u) ? ~u : (u | 0x80000000u);
            atomicMax(&pool[s * 4 + j], mono);
        }
    }

    // ---- re-zero consumed aggregation slices (replaces the 12 memsets) ---------
    if (nsrc == 3) {
        float* z1 = const_cast<float*>(x1);
        float* z2 = const_cast<float*>(x2);
        float4 z = make_float4(0.f, 0.f, 0.f, 0.f);
#pragma unroll
        for (int h = 0; h < 16; h++) {
            int idx = t + h * 256;
            int row = idx >> 5, c4 = idx & 31;
            if (row0 + row < M) {
                *((float4*)(z1 + (size_t)(row0 + row) * D) + c4) = z;
                *((float4*)(z2 + (size_t)(row0 + row) * D) + c4) = z;
            }
        }
    }
}

__global__ void pool_combine_k(unsigned int* __restrict__ pool, float* __restrict__ out)
{
    int t = threadIdx.x;  // 128
    unsigned a = pool[t], bmono = pool[t + D];
    float fa = __uint_as_float((a & 0x80000000u) ? (a & 0x7fffffffu) : ~a);
    float fb = __uint_as_float((bmono & 0x80000000u) ? (bmono & 0x7fffffffu) : ~bmono);
    out[t] = fa + fb;
    pool[t] = 0u;          // re-arm for next graph replay
    pool[t + D] = 0u;
}

// zero pool before out-GEMMs (pool_combine re-zeroes too, but first call needs it
// armed as 0 == mono(-inf); g_pool starts zero, and pool_combine keeps it zero).

// ---------------------------------- launch ---------------------------------------
extern "C" void kernel_launch(void* const* d_in, const int* in_sizes, int n_in,
                              void* d_out, int out_size)
{
    const float* nf_in = (const float*)d_in[0];
    const float* ef_in = (const float*)d_in[1];
    const float* nWc = (const float*)d_in[2];
    const float* nbc = (const float*)d_in[3];
    const float* nWn = (const float*)d_in[4];
    const float* nbn = (const float*)d_in[5];
    const float* nWe = (const float*)d_in[6];
    const float* nbe = (const float*)d_in[7];
    const float* eWc = (const float*)d_in[8];
    const float* ebc = (const float*)d_in[9];
    const float* eWn = (const float*)d_in[10];
    const float* ebn = (const float*)d_in[11];
    const float* eWe = (const float*)d_in[12];
    const float* ebe = (const float*)d_in[13];
    const float* Wno = (const float*)d_in[14];
    const float* bno = (const float*)d_in[15];
    const float* Weo = (const float*)d_in[16];
    const float* beo = (const float*)d_in[17];
    const int* ei  = (const int*)d_in[18];   // [2, E]
    const int* lei = (const int*)d_in[19];   // [2, L]
    const int* nei = (const int*)d_in[20];   // [E]
    const int* nes = (const int*)d_in[21];   // [E]
    const int* eni = (const int*)d_in[22];   // [L]
    const int* ens = (const int*)d_in[23];   // [L]
    float* outp = (float*)d_out;             // [pooled(128) | tn(N*128) | te(E*128)]

    cudaFuncSetAttribute(tc_gemm2_k, cudaFuncAttributeMaxDynamicSharedMemorySize, SM_TOTAL);

    float *nf0, *nf1, *ef0, *ef1, *an, *a1n, *ae, *a1e;
    unsigned int* pool;
    uint32_t* wpk;
    cudaGetSymbolAddress((void**)&nf0, g_nf0);
    cudaGetSymbolAddress((void**)&nf1, g_nf1);
    cudaGetSymbolAddress((void**)&ef0, g_ef0);
    cudaGetSymbolAddress((void**)&ef1, g_ef1);
    cudaGetSymbolAddress((void**)&an,  g_an);
    cudaGetSymbolAddress((void**)&a1n, g_a1n);
    cudaGetSymbolAddress((void**)&ae,  g_ae);
    cudaGetSymbolAddress((void**)&a1e, g_a1e);
    cudaGetSymbolAddress((void**)&pool, g_pool);
    cudaGetSymbolAddress((void**)&wpk, g_wpk);

    // ---- pre-pack weights (one launch; slots 0-8 node, 9-17 edge, 18/19 out) ----
    wprep_all_k<<<(20 * 8192 + 255) / 256, 256>>>(nWc, nWn, nWe, eWc, eWn, eWe,
                                                  Wno, Weo, wpk);

    float* nf_bufs[2] = { nf0, nf1 };
    float* ef_bufs[2] = { ef0, ef1 };

    const float* nf_cur = nf_in;
    const float* ef_cur = ef_in;

    const int SCAT_BLOCKS = 25000;
    const int NGB = (N_NODES + 127) / 128;   // 391
    const int EGB = (N_EDGES + 127) / 128;   // 6250

    for (int i = 0; i < NL; i++) {
        float* nf_next = nf_bufs[i & 1];
        float* ef_next = ef_bufs[i & 1];
        int act = (i < NL - 1);

        // all 4 scatters first (agg buffers are zero: GEMM re-zeroed them last call,
        // .bss zero-init on the very first call)
        scatter_add_k<<<SCAT_BLOCKS, 256>>>(nf_cur, an,  ei,  ei + N_EDGES, N_EDGES);
        scatter_add_k<<<SCAT_BLOCKS, 256>>>(ef_cur, a1n, nei, nes,          N_EDGES);
        scatter_add_k<<<SCAT_BLOCKS, 256>>>(ef_cur, ae,  lei, lei + N_LINE, N_LINE);
        scatter_add_k<<<SCAT_BLOCKS, 256>>>(nf_cur, a1e, eni, ens,          N_LINE);

        // combined node+edge GEMM (also re-zeroes an/a1n/ae/a1e slices)
        tc_gemm2_k<<<NGB + EGB, 256, SM_TOTAL>>>(
            nf_cur, an, a1n,
            wpk + (size_t)(0 + i) * 16384, wpk + (size_t)(3 + i) * 16384,
            wpk + (size_t)(6 + i) * 16384,
            nbc + i * D, nbn + i * D, nbe + i * D,
            nf_next, N_NODES, nullptr,
            ef_cur, ae, a1e,
            wpk + (size_t)(9 + i) * 16384, wpk + (size_t)(12 + i) * 16384,
            wpk + (size_t)(15 + i) * 16384,
            ebc + i * D, ebn + i * D, ebe + i * D,
            ef_next, N_EDGES, nullptr,
            NGB, 3, 1, act);

        nf_cur = nf_next;
        ef_cur = ef_next;
    }

    // combined output linears + fused max-pool (pool is zero: pool_combine re-arms)
    tc_gemm2_k<<<NGB + EGB, 256, SM_TOTAL>>>(
        nf_cur, nullptr, nullptr,
        wpk + (size_t)18 * 16384, nullptr, nullptr,
        bno, nullptr, nullptr,
        outp + D, N_NODES, pool,
        ef_cur, nullptr, nullptr,
        wpk + (size_t)19 * 16384, nullptr, nullptr,
        beo, nullptr, nullptr,
        outp + D + (size_t)N_NODES * D, N_EDGES, pool + D,
        NGB, 1, 0, 0);

    pool_combine_k<<<1, 128>>>(pool, outp);
}

// round 9
// speedup vs baseline: 1.9796x; 1.0156x over previous
#include <cuda_runtime.h>
#include <cstdint>
#include <cstddef>

#define N_NODES 50000
#define N_EDGES 800000
#define N_LINE  800000
#define D 128
#define NL 3

// ---------------- scratch (static device globals; no allocations) ----------------
__device__ float g_nf0[(size_t)N_NODES * D];
__device__ float g_nf1[(size_t)N_NODES * D];
__device__ float g_ef0[(size_t)N_EDGES * D];
__device__ float g_ef1[(size_t)N_EDGES * D];
__device__ float g_an [(size_t)N_NODES * D];   // zero at entry/exit of every call
__device__ float g_a1n[(size_t)N_NODES * D];
__device__ float g_ae [(size_t)N_EDGES * D];
__device__ float g_a1e[(size_t)N_EDGES * D];
__device__ unsigned int g_pool[2 * D];
// packed weights: 20 matrices x [hi 128x64 u32 | lo 128x64 u32]
__device__ uint32_t g_wpk[20 * 16384];

// ---------------- gather + scatter-add (one warp per edge-row, float4 RED) -------
__global__ void scatter_add_k(const float* __restrict__ src, float* __restrict__ dst,
                              const int* __restrict__ gidx, const int* __restrict__ sidx,
                              int count)
{
    int lane  = threadIdx.x & 31;
    int warp  = (blockIdx.x * blockDim.x + threadIdx.x) >> 5;
    int nwarp = (gridDim.x * blockDim.x) >> 5;
    for (int e = warp; e < count; e += nwarp) {
        int g = gidx[e];
        int s = sidx[e];
        float4 v = *((const float4*)(src + (size_t)g * D) + lane);
        atomicAdd((float4*)(dst + (size_t)s * D) + lane, v);
    }
}

// ============================ bf16 split helpers =================================
__device__ __forceinline__ uint32_t packbf(float hi_el, float lo_el) {
    uint32_t r;
    asm("cvt.rn.bf16x2.f32 %0, %1, %2;" : "=r"(r) : "f"(hi_el), "f"(lo_el));
    return r;
}
__device__ __forceinline__ float bf_lo(uint32_t u) { return __uint_as_float(u << 16); }
__device__ __forceinline__ float bf_hi(uint32_t u) { return __uint_as_float(u & 0xFFFF0000u); }

__device__ __forceinline__ void mma16(float* d, uint32_t a0, uint32_t a1, uint32_t a2,
                                      uint32_t a3, uint32_t b0, uint32_t b1)
{
    asm volatile(
        "mma.sync.aligned.m16n8k16.row.col.f32.bf16.bf16.f32 "
        "{%0,%1,%2,%3}, {%4,%5,%6,%7}, {%8,%9}, {%0,%1,%2,%3};"
        : "+f"(d[0]), "+f"(d[1]), "+f"(d[2]), "+f"(d[3])
        : "r"(a0), "r"(a1), "r"(a2), "r"(a3), "r"(b0), "r"(b1));
}

__device__ __forceinline__ void ldm4(uint32_t* r, uint32_t addr) {
    asm volatile("ldmatrix.sync.aligned.m8n8.x4.shared.b16 {%0,%1,%2,%3}, [%4];"
                 : "=r"(r[0]), "=r"(r[1]), "=r"(r[2]), "=r"(r[3]) : "r"(addr));
}
__device__ __forceinline__ void cp16(uint32_t dst, const void* src) {
    asm volatile("cp.async.ca.shared.global [%0], [%1], 16;" :: "r"(dst), "l"(src));
}
#define CP_COMMIT() asm volatile("cp.async.commit_group;" ::: "memory")
#define CP_WAIT0()  asm volatile("cp.async.wait_group 0;" ::: "memory")

// ---------------- weight pre-pack (single launch, all 20 matrices) ---------------
__global__ void wprep_all_k(const float* __restrict__ nWc, const float* __restrict__ nWn,
                            const float* __restrict__ nWe, const float* __restrict__ eWc,
                            const float* __restrict__ eWn, const float* __restrict__ eWe,
                            const float* __restrict__ Wno, const float* __restrict__ Weo,
                            uint32_t* __restrict__ out)
{
    int i = blockIdx.x * blockDim.x + threadIdx.x;
    if (i >= 20 * 8192) return;
    int m = i >> 13, r = i & 8191;
    int n = r >> 6, k2 = r & 63;
    const float* srcs[8] = { nWc, nWn, nWe, eWc, eWn, eWe, Wno, Weo };
    int grp = (m < 18) ? (m / 3) : (m - 18 + 6);
    int loc = (m < 18) ? (m % 3) : 0;
    const float* w = srcs[grp] + (size_t)loc * 16384;
    float x0 = w[(2 * k2) * D + n];
    float x1 = w[(2 * k2 + 1) * D + n];
    uint32_t hi = packbf(x1, x0);
    float r0 = x0 - bf_lo(hi);
    float r1 = x1 - bf_hi(hi);
    uint32_t lo = packbf(r1, r0);
    out[(size_t)m * 16384 + n * 64 + k2]        = hi;
    out[(size_t)m * 16384 + 8192 + n * 64 + k2] = lo;
}

// SMEM (dynamic, 82944 B):
//   [0..512) bias, [512..1024) inv
//   [1024..) two 40960B stages: AsH 128x20u32 | AsL | BsH 128x20u32 | BsL
//   epilogue staging 128x132 f (67584 B) aliases the stage region.
#define SM_TOTAL 82944
#define STG_BYTES 40960

// ========== bf16x3 tensor-core GEMM, cp.async + ldmatrix 2-stage pipeline ========
// nsrc==3 layer GEMMs additionally re-zero their consumed aggregation slices.
__global__ void __launch_bounds__(256, 2) tc_gemm_k(
    const float* __restrict__ x0, const float* __restrict__ x1, const float* __restrict__ x2,
    const uint32_t* __restrict__ pk0, const uint32_t* __restrict__ pk1,
    const uint32_t* __restrict__ pk2,
    const float* __restrict__ b0, const float* __restrict__ b1, const float* __restrict__ b2,
    float* __restrict__ out, int M, int nsrc, int donorm, int act,
    unsigned int* __restrict__ pool)
{
    extern __shared__ char smem[];
    float* bias_s = (float*)smem;
    float* inv_s  = (float*)(smem + 512);
    uint32_t stiles = (uint32_t)__cvta_generic_to_shared(smem) + 1024;

    int t = threadIdx.x;
    int lane = t & 31, wid = t >> 5;
    int warpm = wid >> 2, warpn = wid & 3;
    int gid = lane >> 2, tig = lane & 3;
    int row0 = blockIdx.x * 128;

    if (t < D) {
        float bb = b0[t];
        if (nsrc == 3) bb += b1[t] + b2[t];
        bias_s[t] = bb;
    }

    // thread-constant ldmatrix byte offsets (stride 20 u32 = 80 B per row)
    int arow = warpm * 64 + (lane & 7) + ((lane >> 3) & 1) * 8;
    uint32_t aoff = (uint32_t)(arow * 80) + (lane >> 4) * 16;
    int nrow = warpn * 32 + (lane & 7) + (lane >> 4) * 8;
    uint32_t boff = (uint32_t)(nrow * 80) + ((lane >> 3) & 1) * 16;

    // A loader mapping: 4 float4 per thread
    int ar = t >> 3;        // rows ar, ar+32, ar+64, ar+96
    int aj = t & 7;         // float4 index within 32-float row

    float acc[4][4][4];
#pragma unroll
    for (int i = 0; i < 4; i++)
#pragma unroll
        for (int j = 0; j < 4; j++)
#pragma unroll
            for (int k = 0; k < 4; k++) acc[i][j][k] = 0.f;

    const float* xs[3] = { x0, x1, x2 };
    const uint32_t* ps[3] = { pk0, pk1, pk2 };
    const int nch = nsrc * 4;

    float4 av[4];

    // ---- prologue: chunk 0 into stage 0 ----------------------------------------
    {
        const float* src = xs[0];
#pragma unroll
        for (int h = 0; h < 4; h++) {
            int r = ar + h * 32;
            av[h] = make_float4(0.f, 0.f, 0.f, 0.f);
            if (row0 + r < M)
                av[h] = *(const float4*)(src + (size_t)(row0 + r) * D + aj * 4);
        }
        const uint32_t* sH = ps[0];
        const uint32_t* sL = ps[0] + 8192;
        uint32_t dH = stiles + 20480, dL = stiles + 30720;
#pragma unroll
        for (int i = 0; i < 2; i++) {
            int idx = t + i * 256;
            int n = idx >> 2, j4 = idx & 3;
            cp16(dH + n * 80 + j4 * 16, sH + n * 64 + j4 * 4);
            cp16(dL + n * 80 + j4 * 16, sL + n * 64 + j4 * 4);
        }
        CP_COMMIT();
        uint32_t* pH = (uint32_t*)(smem + 1024);
        uint32_t* pL = (uint32_t*)(smem + 1024 + 10240);
#pragma unroll
        for (int h = 0; h < 4; h++) {
            int r = ar + h * 32;
            float4 v = av[h];
            uint32_t h0 = packbf(v.y, v.x), h1 = packbf(v.w, v.z);
            float r0 = v.x - bf_lo(h0), r1 = v.y - bf_hi(h0);
            float r2 = v.z - bf_lo(h1), r3 = v.w - bf_hi(h1);
            *(uint2*)(pH + r * 20 + aj * 2) = make_uint2(h0, h1);
            *(uint2*)(pL + r * 20 + aj * 2) = make_uint2(packbf(r1, r0), packbf(r3, r2));
        }
        CP_WAIT0();
    }
    __syncthreads();

    // ---- main pipelined loop ----------------------------------------------------
    for (int c = 0; c < nch; c++) {
        int s = c & 1;
        int have_next = (c + 1 < nch);

        if (have_next) {
            int c1 = c + 1;
            const float* src = xs[c1 >> 2];
            int kofs = (c1 & 3) * 32;
#pragma unroll
            for (int h = 0; h < 4; h++) {
                int r = ar + h * 32;
                av[h] = make_float4(0.f, 0.f, 0.f, 0.f);
                if (row0 + r < M)
                    av[h] = *(const float4*)(src + (size_t)(row0 + r) * D + kofs + aj * 4);
            }
            const uint32_t* pk = ps[c1 >> 2];
            int k2o = (c1 & 3) * 16;
            const uint32_t* sH = pk + k2o;
            const uint32_t* sL = pk + 8192 + k2o;
            uint32_t sb = stiles + (s ^ 1) * STG_BYTES;
            uint32_t dH = sb + 20480, dL = sb + 30720;
#pragma unroll
            for (int i = 0; i < 2; i++) {
                int idx = t + i * 256;
                int n = idx >> 2, j4 = idx & 3;
                cp16(dH + n * 80 + j4 * 16, sH + n * 64 + j4 * 4);
                cp16(dL + n * 80 + j4 * 16, sL + n * 64 + j4 * 4);
            }
            CP_COMMIT();
        }

        // ---- MMA on stage s via ldmatrix ----------------------------------------
        {
            uint32_t bAH = stiles + s * STG_BYTES;
            uint32_t bAL = bAH + 10240;
            uint32_t bBH = bAH + 20480;
            uint32_t bBL = bAH + 30720;
#pragma unroll
            for (int ks = 0; ks < 2; ks++) {
                uint32_t kso = ks * 32;
                uint32_t bh[4][2], bl[4][2], r4[4];
#pragma unroll
                for (int p = 0; p < 2; p++) {
                    ldm4(r4, bBH + boff + p * 1280 + kso);
                    bh[2 * p][0] = r4[0]; bh[2 * p][1] = r4[1];
                    bh[2 * p + 1][0] = r4[2]; bh[2 * p + 1][1] = r4[3];
                    ldm4(r4, bBL + boff + p * 1280 + kso);
                    bl[2 * p][0] = r4[0]; bl[2 * p][1] = r4[1];
                    bl[2 * p + 1][0] = r4[2]; bl[2 * p + 1][1] = r4[3];
                }
#pragma unroll
                for (int mf = 0; mf < 4; mf++) {
                    uint32_t ah[4], al[4];
                    ldm4(ah, bAH + aoff + mf * 1280 + kso);
                    ldm4(al, bAL + aoff + mf * 1280 + kso);
#pragma unroll
                    for (int nf = 0; nf < 4; nf++) {
                        mma16(acc[mf][nf], ah[0], ah[1], ah[2], ah[3], bh[nf][0], bh[nf][1]);
                        mma16(acc[mf][nf], ah[0], ah[1], ah[2], ah[3], bl[nf][0], bl[nf][1]);
                        mma16(acc[mf][nf], al[0], al[1], al[2], al[3], bh[nf][0], bh[nf][1]);
                    }
                }
            }
        }

        if (have_next) {
            uint32_t* pH = (uint32_t*)(smem + 1024 + (s ^ 1) * STG_BYTES);
            uint32_t* pL = pH + 2560;
#pragma unroll
            for (int h = 0; h < 4; h++) {
                int r = ar + h * 32;
                float4 v = av[h];
                uint32_t h0 = packbf(v.y, v.x), h1 = packbf(v.w, v.z);
                float r0 = v.x - bf_lo(h0), r1 = v.y - bf_hi(h0);
                float r2 = v.z - bf_lo(h1), r3 = v.w - bf_hi(h1);
                *(uint2*)(pH + r * 20 + aj * 2) = make_uint2(h0, h1);
                *(uint2*)(pL + r * 20 + aj * 2) = make_uint2(packbf(r1, r0), packbf(r3, r2));
            }
            CP_WAIT0();
        }
        __syncthreads();
    }

    // ---- epilogue: stage acc + bias into smem (aliases operand tiles) ----------
    float* stg = (float*)(smem + 1024);                // 128 x 132 floats
#pragma unroll
    for (int mf = 0; mf < 4; mf++) {
        int row = warpm * 64 + mf * 16 + gid;
#pragma unroll
        for (int nf = 0; nf < 4; nf++) {
            int col = warpn * 32 + nf * 8 + 2 * tig;
            stg[row * 132 + col]           = acc[mf][nf][0] + bias_s[col];
            stg[row * 132 + col + 1]       = acc[mf][nf][1] + bias_s[col + 1];
            stg[(row + 8) * 132 + col]     = acc[mf][nf][2] + bias_s[col];
            stg[(row + 8) * 132 + col + 1] = acc[mf][nf][3] + bias_s[col + 1];
        }
    }
    __syncthreads();

    // ---- pass1: per-row inverse L2 norm ----------------------------------------
    if (donorm && t < 128) {
        float ssq = 0.f;
#pragma unroll
        for (int j = 0; j < 32; j++) {
            float4 v = *(float4*)(stg + t * 132 + j * 4);
            ssq += v.x * v.x + v.y * v.y + v.z * v.z + v.w * v.w;
        }
        inv_s[t] = 1.0f / fmaxf(sqrtf(ssq), 1e-12f);
    }
    __syncthreads();

    // ---- pass2: normalize/act, coalesced store, fused column max-pool ----------
    int s = t & 31;
    float4 pmax = make_float4(-3.402823466e38f, -3.402823466e38f,
                              -3.402823466e38f, -3.402823466e38f);
#pragma unroll
    for (int h = 0; h < 16; h++) {
        int idx = t + h * 256;
        int row = idx >> 5;
        float4 v = *(float4*)(stg + row * 132 + s * 4);
        if (donorm) {
            float iv = inv_s[row];
            v.x *= iv; v.y *= iv; v.z *= iv; v.w *= iv;
            if (act) {
                v.x = (v.x >= 0.f) ? v.x : 0.01f * v.x;
                v.y = (v.y >= 0.f) ? v.y : 0.01f * v.y;
                v.z = (v.z >= 0.f) ? v.z : 0.01f * v.z;
                v.w = (v.w >= 0.f) ? v.w : 0.01f * v.w;
            }
        }
        if (row0 + row < M) {
            *(float4*)(out + (size_t)(row0 + row) * D + s * 4) = v;
            if (pool) {
                pmax.x = fmaxf(pmax.x, v.x); pmax.y = fmaxf(pmax.y, v.y);
                pmax.z = fmaxf(pmax.z, v.z); pmax.w = fmaxf(pmax.w, v.w);
            }
        }
    }
    if (pool) {
        float pv[4] = { pmax.x, pmax.y, pmax.z, pmax.w };
#pragma unroll
        for (int j = 0; j < 4; j++) {
            unsigned u = __float_as_uint(pv[j]);
            unsigned mono = (u & 0x80000000u) ? ~u : (u | 0x80000000u);
            atomicMax(&pool[s * 4 + j], mono);
        }
    }

    // ---- re-zero consumed aggregation slices (replaces memsets) ----------------
    if (nsrc == 3) {
        float* z1 = const_cast<float*>(x1);
        float* z2 = const_cast<float*>(x2);
        float4 z = make_float4(0.f, 0.f, 0.f, 0.f);
#pragma unroll
        for (int h = 0; h < 16; h++) {
            int idx = t + h * 256;
            int row = idx >> 5, c4 = idx & 31;
            if (row0 + row < M) {
                *((float4*)(z1 + (size_t)(row0 + row) * D) + c4) = z;
                *((float4*)(z2 + (size_t)(row0 + row) * D) + c4) = z;
            }
        }
    }
}

__global__ void pool_combine_k(unsigned int* __restrict__ pool, float* __restrict__ out)
{
    int t = threadIdx.x;  // 128
    unsigned a = pool[t], bmono = pool[t + D];
    float fa = __uint_as_float((a & 0x80000000u) ? (a & 0x7fffffffu) : ~a);
    float fb = __uint_as_float((bmono & 0x80000000u) ? (bmono & 0x7fffffffu) : ~bmono);
    out[t] = fa + fb;
    pool[t] = 0u;          // re-arm for next graph replay
    pool[t + D] = 0u;
}

// --------- one-time stream/event setup (first, uncaptured, call) -----------------
struct AsyncCtx {
    cudaStream_t s1;
    cudaEvent_t evF, evGN, evGE, evJ;
    AsyncCtx() {
        cudaStreamCreateWithFlags(&s1, cudaStreamNonBlocking);
        cudaEventCreateWithFlags(&evF,  cudaEventDisableTiming);
        cudaEventCreateWithFlags(&evGN, cudaEventDisableTiming);
        cudaEventCreateWithFlags(&evGE, cudaEventDisableTiming);
        cudaEventCreateWithFlags(&evJ,  cudaEventDisableTiming);
    }
};

// ---------------------------------- launch ---------------------------------------
extern "C" void kernel_launch(void* const* d_in, const int* in_sizes, int n_in,
                              void* d_out, int out_size)
{
    static AsyncCtx ax;   // created on the uncaptured correctness call

    const float* nf_in = (const float*)d_in[0];
    const float* ef_in = (const float*)d_in[1];
    const float* nWc = (const float*)d_in[2];
    const float* nbc = (const float*)d_in[3];
    const float* nWn = (const float*)d_in[4];
    const float* nbn = (const float*)d_in[5];
    const float* nWe = (const float*)d_in[6];
    const float* nbe = (const float*)d_in[7];
    const float* eWc = (const float*)d_in[8];
    const float* ebc = (const float*)d_in[9];
    const float* eWn = (const float*)d_in[10];
    const float* ebn = (const float*)d_in[11];
    const float* eWe = (const float*)d_in[12];
    const float* ebe = (const float*)d_in[13];
    const float* Wno = (const float*)d_in[14];
    const float* bno = (const float*)d_in[15];
    const float* Weo = (const float*)d_in[16];
    const float* beo = (const float*)d_in[17];
    const int* ei  = (const int*)d_in[18];   // [2, E]
    const int* lei = (const int*)d_in[19];   // [2, L]
    const int* nei = (const int*)d_in[20];   // [E]
    const int* nes = (const int*)d_in[21];   // [E]
    const int* eni = (const int*)d_in[22];   // [L]
    const int* ens = (const int*)d_in[23];   // [L]
    float* outp = (float*)d_out;             // [pooled(128) | tn(N*128) | te(E*128)]

    cudaFuncSetAttribute(tc_gemm_k, cudaFuncAttributeMaxDynamicSharedMemorySize, SM_TOTAL);

    float *nf0, *nf1, *ef0, *ef1, *an, *a1n, *ae, *a1e;
    unsigned int* pool;
    uint32_t* wpk;
    cudaGetSymbolAddress((void**)&nf0, g_nf0);
    cudaGetSymbolAddress((void**)&nf1, g_nf1);
    cudaGetSymbolAddress((void**)&ef0, g_ef0);
    cudaGetSymbolAddress((void**)&ef1, g_ef1);
    cudaGetSymbolAddress((void**)&an,  g_an);
    cudaGetSymbolAddress((void**)&a1n, g_a1n);
    cudaGetSymbolAddress((void**)&ae,  g_ae);
    cudaGetSymbolAddress((void**)&a1e, g_a1e);
    cudaGetSymbolAddress((void**)&pool, g_pool);
    cudaGetSymbolAddress((void**)&wpk, g_wpk);

    cudaStream_t s0 = 0, s1 = ax.s1;

    // ---- pre-pack weights, then fork s1 off the capturing stream ----------------
    wprep_all_k<<<(20 * 8192 + 255) / 256, 256, 0, s0>>>(nWc, nWn, nWe, eWc, eWn, eWe,
                                                         Wno, Weo, wpk);
    cudaEventRecord(ax.evF, s0);
    cudaStreamWaitEvent(s1, ax.evF, 0);

    float* nf_bufs[2] = { nf0, nf1 };
    float* ef_bufs[2] = { ef0, ef1 };

    const float* nf_cur = nf_in;
    const float* ef_cur = ef_in;

    const int SCAT_BLOCKS = 25000;
    const int NGB = (N_NODES + 127) / 128;   // 391
    const int EGB = (N_EDGES + 127) / 128;   // 6250

    for (int i = 0; i < NL; i++) {
        float* nf_next = nf_bufs[i & 1];
        float* ef_next = ef_bufs[i & 1];
        int act = (i < NL - 1);

        // -------- node chain on s0, edge chain on s1 --------
        // S1 (s0): an += nf_cur[ei0] -> ei1   (nf_cur produced on s0)
        scatter_add_k<<<SCAT_BLOCKS, 256, 0, s0>>>(nf_cur, an, ei, ei + N_EDGES, N_EDGES);

        // S3 (s1): ae += ef_cur[lei0] -> lei1 (ef_cur produced on s1)
        scatter_add_k<<<SCAT_BLOCKS, 256, 0, s1>>>(ef_cur, ae, lei, lei + N_LINE, N_LINE);

        // S4 (s1): a1e += nf_cur[eni] -> ens  (needs prev G_node output)
        if (i > 0) cudaStreamWaitEvent(s1, ax.evGN, 0);
        scatter_add_k<<<SCAT_BLOCKS, 256, 0, s1>>>(nf_cur, a1e, eni, ens, N_LINE);

        // S2 (s0): a1n += ef_cur[nei] -> nes  (needs prev G_edge output)
        if (i > 0) cudaStreamWaitEvent(s0, ax.evGE, 0);
        scatter_add_k<<<SCAT_BLOCKS, 256, 0, s0>>>(ef_cur, a1n, nei, nes, N_EDGES);

        // G_node (s0): consumes an/a1n (re-zeroes them), writes nf_next
        tc_gemm_k<<<NGB, 256, SM_TOTAL, s0>>>(nf_cur, an, a1n,
                                              wpk + (size_t)(0 + i) * 16384,
                                              wpk + (size_t)(3 + i) * 16384,
                                              wpk + (size_t)(6 + i) * 16384,
                                              nbc + i * D, nbn + i * D, nbe + i * D,
                                              nf_next, N_NODES, 3, 1, act, nullptr);
        cudaEventRecord(ax.evGN, s0);

        // G_edge (s1): consumes ae/a1e (re-zeroes them), writes ef_next
        tc_gemm_k<<<EGB, 256, SM_TOTAL, s1>>>(ef_cur, ae, a1e,
                                              wpk + (size_t)(9 + i) * 16384,
                                              wpk + (size_t)(12 + i) * 16384,
                                              wpk + (size_t)(15 + i) * 16384,
                                              ebc + i * D, ebn + i * D, ebe + i * D,
                                              ef_next, N_EDGES, 3, 1, act, nullptr);
        cudaEventRecord(ax.evGE, s1);

        nf_cur = nf_next;
        ef_cur = ef_next;
    }

    // ---- output linears + fused max-pool, concurrent on both streams -----------
    tc_gemm_k<<<NGB, 256, SM_TOTAL, s0>>>(nf_cur, nullptr, nullptr,
                                          wpk + (size_t)18 * 16384, nullptr, nullptr,
                                          bno, nullptr, nullptr,
                                          outp + D, N_NODES, 1, 0, 0, pool);
    tc_gemm_k<<<EGB, 256, SM_TOTAL, s1>>>(ef_cur, nullptr, nullptr,
                                          wpk + (size_t)19 * 16384, nullptr, nullptr,
                                          beo, nullptr, nullptr,
                                          outp + D + (size_t)N_NODES * D, N_EDGES,
                                          1, 0, 0, pool + D);
    cudaEventRecord(ax.evJ, s1);
    cudaStreamWaitEvent(s0, ax.evJ, 0);     // join s1 back into the capture stream

    pool_combine_k<<<1, 128, 0, s0>>>(pool, outp);
}